// round 1
// baseline (speedup 1.0000x reference)
#include <cuda_runtime.h>
#include <cstdint>

#define NTOK  32768
#define DIMD  256
#define HEADS 8
#define DH    64
#define MSAH  128
#define MSAW  256
#define PLD   3072   // P row stride: [wq(512) | wkv(1024) | hq(512) | hkv(1024)]
#define OLD   1024   // O row stride: [Ow(512) | Oh(512)]

// Scratch (device-global: allocation inside kernel_launch is forbidden)
__device__ float g_P[(size_t)NTOK * PLD];     // 402 MB projections
__device__ float g_O[(size_t)NTOK * OLD];     // 134 MB attention outputs
__device__ float g_Sh[HEADS * 256 * 256];     // 2 MB tied-attention logits

// ---------------------------------------------------------------------------
// Generic 128x128x8 register-tiled SGEMM.
// C[M x N] = A[M x K] @ B[K x N] (+ bias1 + bias2 if bias1 != nullptr)
// B rows come from B1 for k < ksplit, else from B2 (row k-ksplit).
// M, N multiples of 128; K multiple of 8. Row-major everything.
// ---------------------------------------------------------------------------
__global__ __launch_bounds__(256) void sgemm128(
    const float* __restrict__ A, int lda,
    const float* __restrict__ B1, const float* __restrict__ B2, int ldb, int ksplit,
    float* __restrict__ C, int ldc,
    const float* __restrict__ bias1, const float* __restrict__ bias2,
    int K)
{
    __shared__ float As[8][128];
    __shared__ float Bs[8][128];
    const int tid = threadIdx.x;
    const int i0 = blockIdx.y * 128;
    const int j0 = blockIdx.x * 128;
    const int ty = tid >> 4, tx = tid & 15;
    const int rowA = tid >> 1, kA = (tid & 1) * 4;   // 128 rows x 8 k (float4)
    const int kB = tid >> 5, colB = (tid & 31) * 4;  // 8 k x 128 cols (float4)

    float acc[8][8];
#pragma unroll
    for (int i = 0; i < 8; i++)
#pragma unroll
        for (int j = 0; j < 8; j++) acc[i][j] = 0.f;

    for (int k0 = 0; k0 < K; k0 += 8) {
        float4 a4 = *(const float4*)(A + (size_t)(i0 + rowA) * lda + (k0 + kA));
        const float* Bsrc = (k0 < ksplit)
            ? (B1 + (size_t)(k0 + kB) * ldb)
            : (B2 + (size_t)(k0 - ksplit + kB) * ldb);
        float4 b4 = *(const float4*)(Bsrc + j0 + colB);

        As[kA + 0][rowA] = a4.x; As[kA + 1][rowA] = a4.y;
        As[kA + 2][rowA] = a4.z; As[kA + 3][rowA] = a4.w;
        *(float4*)&Bs[kB][colB] = b4;
        __syncthreads();

#pragma unroll
        for (int kk = 0; kk < 8; kk++) {
            float a[8], b[8];
#pragma unroll
            for (int u = 0; u < 8; u++) { a[u] = As[kk][ty * 8 + u]; b[u] = Bs[kk][tx * 8 + u]; }
#pragma unroll
            for (int i = 0; i < 8; i++)
#pragma unroll
                for (int j = 0; j < 8; j++) acc[i][j] = fmaf(a[i], b[j], acc[i][j]);
        }
        __syncthreads();
    }

#pragma unroll
    for (int i = 0; i < 8; i++) {
        int row = i0 + ty * 8 + i;
#pragma unroll
        for (int j = 0; j < 8; j += 4) {
            int col = j0 + tx * 8 + j;
            float4 v;
            v.x = acc[i][j]; v.y = acc[i][j + 1]; v.z = acc[i][j + 2]; v.w = acc[i][j + 3];
            if (bias1) {
                v.x += bias1[col + 0] + bias2[col + 0];
                v.y += bias1[col + 1] + bias2[col + 1];
                v.z += bias1[col + 2] + bias2[col + 2];
                v.w += bias1[col + 3] + bias2[col + 3];
            }
            *(float4*)(C + (size_t)row * ldc + col) = v;
        }
    }
}

// ---------------------------------------------------------------------------
// Column-wise attention (w branch): per (column cw, head H), 128x128 attention
// over the 128 MSA rows. Everything staged in dynamic smem (ld=129 padding).
// Writes Ow into g_O cols [0,512).
// ---------------------------------------------------------------------------
#define SQ_LD 129
#define SS_LD 129
#define ATTN_SMEM_FLOATS (2 * 64 * SQ_LD + 128 * SS_LD)  // 8256*2 + 16512 = 33024

__global__ __launch_bounds__(256) void attn_w_kernel()
{
    extern __shared__ float sm[];
    float* sQ = sm;                  // Q^T : [64 dh][128 r], ld 129
    float* sK = sm + 64 * SQ_LD;     // K^T : [64 dh][128 r], ld 129
    float* sS = sm + 2 * 64 * SQ_LD; // S   : [128][128], ld 129
    float* sV = sm;                  // V   : [128 j][64 dh]  (reuses sQ after S)

    const int cw = blockIdx.x;
    const int Hh = blockIdx.y;
    const int tid = threadIdx.x;

    // Load Q, K (transposed into smem)
    for (int idx = tid * 4; idx < 8192; idx += 1024) {
        int r = idx >> 6, dh = idx & 63;
        const float* p = g_P + (size_t)(r * 256 + cw) * PLD + Hh * 64 + dh;
        float4 q4 = *(const float4*)p;
        float4 k4 = *(const float4*)(p + 512);
        sQ[(dh + 0) * SQ_LD + r] = q4.x; sQ[(dh + 1) * SQ_LD + r] = q4.y;
        sQ[(dh + 2) * SQ_LD + r] = q4.z; sQ[(dh + 3) * SQ_LD + r] = q4.w;
        sK[(dh + 0) * SQ_LD + r] = k4.x; sK[(dh + 1) * SQ_LD + r] = k4.y;
        sK[(dh + 2) * SQ_LD + r] = k4.z; sK[(dh + 3) * SQ_LD + r] = k4.w;
    }
    __syncthreads();

    // S = scale * Q K^T  (16x16 threads, 8x8 micro-tile)
    {
        const int ty = tid >> 4, tx = tid & 15;
        float acc[8][8];
#pragma unroll
        for (int i = 0; i < 8; i++)
#pragma unroll
            for (int j = 0; j < 8; j++) acc[i][j] = 0.f;
#pragma unroll 4
        for (int dh = 0; dh < 64; dh++) {
            float a[8], b[8];
#pragma unroll
            for (int u = 0; u < 8; u++) {
                a[u] = sQ[dh * SQ_LD + ty * 8 + u];
                b[u] = sK[dh * SQ_LD + tx * 8 + u];
            }
#pragma unroll
            for (int i = 0; i < 8; i++)
#pragma unroll
                for (int j = 0; j < 8; j++) acc[i][j] = fmaf(a[i], b[j], acc[i][j]);
        }
#pragma unroll
        for (int i = 0; i < 8; i++)
#pragma unroll
            for (int j = 0; j < 8; j++)
                sS[(ty * 8 + i) * SS_LD + tx * 8 + j] = acc[i][j] * 0.125f;
    }
    __syncthreads();

    // Load V (overwrites sQ region — all sQ/sK reads completed above)
    for (int idx = tid * 4; idx < 8192; idx += 1024) {
        int r = idx >> 6, dh = idx & 63;
        float4 v4 = *(const float4*)(g_P + (size_t)(r * 256 + cw) * PLD + 1024 + Hh * 64 + dh);
        *(float4*)&sV[r * 64 + dh] = v4;
    }
    // Row softmax (one thread per row; ld-129 keeps it conflict-free)
    if (tid < 128) {
        float* row = sS + tid * SS_LD;
        float m = -1e30f;
        for (int j = 0; j < 128; j++) m = fmaxf(m, row[j]);
        float s = 0.f;
        for (int j = 0; j < 128; j++) { float e = __expf(row[j] - m); row[j] = e; s += e; }
        float inv = 1.f / s;
        for (int j = 0; j < 128; j++) row[j] *= inv;
    }
    __syncthreads();

    // O = A V  (16x16 threads, 8 rows x 4 dh each)
    {
        const int ty = tid >> 4, tx = tid & 15;
        float o[8][4];
#pragma unroll
        for (int i = 0; i < 8; i++)
#pragma unroll
            for (int j = 0; j < 4; j++) o[i][j] = 0.f;
#pragma unroll 4
        for (int j = 0; j < 128; j++) {
            float4 v = *(const float4*)&sV[j * 64 + tx * 4];
#pragma unroll
            for (int i = 0; i < 8; i++) {
                float a = sS[(ty * 8 + i) * SS_LD + j];
                o[i][0] = fmaf(a, v.x, o[i][0]);
                o[i][1] = fmaf(a, v.y, o[i][1]);
                o[i][2] = fmaf(a, v.z, o[i][2]);
                o[i][3] = fmaf(a, v.w, o[i][3]);
            }
        }
#pragma unroll
        for (int i = 0; i < 8; i++) {
            int r = ty * 8 + i;
            float4 w; w.x = o[i][0]; w.y = o[i][1]; w.z = o[i][2]; w.w = o[i][3];
            *(float4*)(g_O + (size_t)(r * 256 + cw) * OLD + Hh * 64 + tx * 4) = w;
        }
    }
}

// ---------------------------------------------------------------------------
// Tied row attention, step 1: dots[H,i,j] = tie_scale * sum_{r,dh} q[r,i,H,dh]*k[r,j,H,dh]
// GEMM with M=N=256, K=8192. 64x64 tile per block, 4x4 micro-tile.
// ---------------------------------------------------------------------------
__global__ __launch_bounds__(256) void dots_h_kernel()
{
    __shared__ float Ast[64 * 65];  // [dh][i]
    __shared__ float Bst[64 * 65];  // [dh][j]
    const int i0 = blockIdx.x * 64;
    const int j0 = blockIdx.y * 64;
    const int Hh = blockIdx.z;
    const int tid = threadIdx.x;
    const int ty = tid >> 4, tx = tid & 15;

    float acc[4][4];
#pragma unroll
    for (int i = 0; i < 4; i++)
#pragma unroll
        for (int j = 0; j < 4; j++) acc[i][j] = 0.f;

    for (int r = 0; r < 128; r++) {
        __syncthreads();
        for (int idx = tid * 4; idx < 4096; idx += 1024) {
            int row = idx >> 6, c = idx & 63;
            float4 a4 = *(const float4*)(g_P + (size_t)(r * 256 + i0 + row) * PLD + 1536 + Hh * 64 + c);
            float4 b4 = *(const float4*)(g_P + (size_t)(r * 256 + j0 + row) * PLD + 2048 + Hh * 64 + c);
            Ast[(c + 0) * 65 + row] = a4.x; Ast[(c + 1) * 65 + row] = a4.y;
            Ast[(c + 2) * 65 + row] = a4.z; Ast[(c + 3) * 65 + row] = a4.w;
            Bst[(c + 0) * 65 + row] = b4.x; Bst[(c + 1) * 65 + row] = b4.y;
            Bst[(c + 2) * 65 + row] = b4.z; Bst[(c + 3) * 65 + row] = b4.w;
        }
        __syncthreads();
#pragma unroll 8
        for (int dh = 0; dh < 64; dh++) {
            float a[4], b[4];
#pragma unroll
            for (int u = 0; u < 4; u++) {
                a[u] = Ast[dh * 65 + ty * 4 + u];
                b[u] = Bst[dh * 65 + tx * 4 + u];
            }
#pragma unroll
            for (int i = 0; i < 4; i++)
#pragma unroll
                for (int j = 0; j < 4; j++) acc[i][j] = fmaf(a[i], b[j], acc[i][j]);
        }
    }
    const float tsc = 0.011048543456039806f;  // 64^-0.5 * 128^-0.5
#pragma unroll
    for (int i = 0; i < 4; i++)
#pragma unroll
        for (int j = 0; j < 4; j++)
            g_Sh[Hh * 65536 + (i0 + ty * 4 + i) * 256 + j0 + tx * 4 + j] = acc[i][j] * tsc;
}

// Tied row attention, step 2: softmax over j for each of 8*256 rows of 256.
__global__ __launch_bounds__(256) void softmax_h_kernel()
{
    float* p = g_Sh + (size_t)blockIdx.x * 256;
    const int tid = threadIdx.x;
    __shared__ float red[256];
    float v = p[tid];
    red[tid] = v;
    __syncthreads();
#pragma unroll
    for (int s = 128; s > 0; s >>= 1) {
        if (tid < s) red[tid] = fmaxf(red[tid], red[tid + s]);
        __syncthreads();
    }
    float m = red[0];
    __syncthreads();
    float e = __expf(v - m);
    red[tid] = e;
    __syncthreads();
#pragma unroll
    for (int s = 128; s > 0; s >>= 1) {
        if (tid < s) red[tid] += red[tid + s];
        __syncthreads();
    }
    p[tid] = e / red[0];
}

// ---------------------------------------------------------------------------
// Tied row attention, step 3: O[r,i,H,dh] = sum_j attn[H,i,j] * v[r,j,H,dh]
// Per (r, i-tile, H): 64x64 output tile, K=256 over j. Writes g_O cols [512,1024).
// ---------------------------------------------------------------------------
__global__ __launch_bounds__(256) void av_h_kernel()
{
    __shared__ float Ast[64 * 65];  // attn^T chunk: [j][i]
    __shared__ float Vs[64 * 64];   // V chunk: [j][dh]
    const int r  = blockIdx.x;
    const int i0 = blockIdx.y * 64;
    const int Hh = blockIdx.z;
    const int tid = threadIdx.x;
    const int ty = tid >> 4, tx = tid & 15;

    float acc[4][4];
#pragma unroll
    for (int i = 0; i < 4; i++)
#pragma unroll
        for (int j = 0; j < 4; j++) acc[i][j] = 0.f;

    for (int jc = 0; jc < 256; jc += 64) {
        __syncthreads();
        for (int idx = tid * 4; idx < 4096; idx += 1024) {
            int row = idx >> 6, c = idx & 63;
            float4 a4 = *(const float4*)(g_Sh + Hh * 65536 + (i0 + row) * 256 + jc + c);
            Ast[(c + 0) * 65 + row] = a4.x; Ast[(c + 1) * 65 + row] = a4.y;
            Ast[(c + 2) * 65 + row] = a4.z; Ast[(c + 3) * 65 + row] = a4.w;
            float4 v4 = *(const float4*)(g_P + (size_t)(r * 256 + jc + row) * PLD + 2560 + Hh * 64 + c);
            *(float4*)&Vs[row * 64 + c] = v4;
        }
        __syncthreads();
#pragma unroll 8
        for (int jj = 0; jj < 64; jj++) {
            float a[4];
#pragma unroll
            for (int u = 0; u < 4; u++) a[u] = Ast[jj * 65 + ty * 4 + u];
            float4 bv = *(const float4*)&Vs[jj * 64 + tx * 4];
#pragma unroll
            for (int i = 0; i < 4; i++) {
                acc[i][0] = fmaf(a[i], bv.x, acc[i][0]);
                acc[i][1] = fmaf(a[i], bv.y, acc[i][1]);
                acc[i][2] = fmaf(a[i], bv.z, acc[i][2]);
                acc[i][3] = fmaf(a[i], bv.w, acc[i][3]);
            }
        }
    }
#pragma unroll
    for (int i = 0; i < 4; i++) {
        int ii = i0 + ty * 4 + i;
        float4 w; w.x = acc[i][0]; w.y = acc[i][1]; w.z = acc[i][2]; w.w = acc[i][3];
        *(float4*)(g_O + (size_t)(r * 256 + ii) * OLD + 512 + Hh * 64 + tx * 4) = w;
    }
}

// ---------------------------------------------------------------------------
extern "C" void kernel_launch(void* const* d_in, const int* in_sizes, int n_in,
                              void* d_out, int out_size)
{
    const float* x      = (const float*)d_in[0];
    const float* wq_w   = (const float*)d_in[1];
    const float* wkv_w  = (const float*)d_in[2];
    const float* wout_w = (const float*)d_in[3];
    const float* wout_b = (const float*)d_in[4];
    const float* hq_w   = (const float*)d_in[5];
    const float* hkv_w  = (const float*)d_in[6];
    const float* hout_w = (const float*)d_in[7];
    const float* hout_b = (const float*)d_in[8];
    float* out = (float*)d_out;

    float *P, *O;
    cudaGetSymbolAddress((void**)&P, g_P);
    cudaGetSymbolAddress((void**)&O, g_O);

    dim3 blk(256);

    // Projections: P = x @ [wq | wkv | hq | hkv]   (M=32768, K=256)
    sgemm128<<<dim3(4,  NTOK / 128), blk>>>(x, DIMD, wq_w,  wq_w,  512,  1 << 20, P + 0,    PLD, nullptr, nullptr, DIMD);
    sgemm128<<<dim3(8,  NTOK / 128), blk>>>(x, DIMD, wkv_w, wkv_w, 1024, 1 << 20, P + 512,  PLD, nullptr, nullptr, DIMD);
    sgemm128<<<dim3(4,  NTOK / 128), blk>>>(x, DIMD, hq_w,  hq_w,  512,  1 << 20, P + 1536, PLD, nullptr, nullptr, DIMD);
    sgemm128<<<dim3(8,  NTOK / 128), blk>>>(x, DIMD, hkv_w, hkv_w, 1024, 1 << 20, P + 2048, PLD, nullptr, nullptr, DIMD);

    // Column-wise attention (w branch) -> g_O[:, 0:512)
    cudaFuncSetAttribute(attn_w_kernel, cudaFuncAttributeMaxDynamicSharedMemorySize,
                         ATTN_SMEM_FLOATS * (int)sizeof(float));
    attn_w_kernel<<<dim3(256, 8), blk, ATTN_SMEM_FLOATS * sizeof(float)>>>();

    // Tied row attention (h branch) -> g_O[:, 512:1024)
    dots_h_kernel<<<dim3(4, 4, 8), blk>>>();
    softmax_h_kernel<<<dim3(2048), blk>>>();
    av_h_kernel<<<dim3(128, 4, 8), blk>>>();

    // out = Ow @ wout_w + Oh @ hout_w + wout_b + hout_b   (K=1024 fused)
    sgemm128<<<dim3(2, NTOK / 128), blk>>>(O, OLD, wout_w, hout_w, DIMD, 512, out, DIMD,
                                           wout_b, hout_b, 1024);
}

// round 3
// speedup vs baseline: 1.2696x; 1.2696x over previous
#include <cuda_runtime.h>
#include <cuda_bf16.h>
#include <cstdint>

#define NTOK  32768
#define DIMD  256
#define HEADS 8
#define DH    64
#define MSAH  128
#define MSAW  256
#define PLD   3072   // P row stride: [wq(512) | wkv(1024) | hq(512) | hkv(1024)]
#define OLD   1024   // O cols: [Ow(512) | Oh(512)] (bf16 hi/lo split buffers)

// ---------------------------------------------------------------------------
// Scratch (device-global: allocation inside kernel_launch is forbidden)
// ---------------------------------------------------------------------------
__device__ float g_P[(size_t)NTOK * PLD];     // 402 MB projections (fp32 for attention)
__device__ float g_Sh[HEADS * 256 * 256];     // 2 MB tied-attention logits

__device__ __nv_bfloat16 g_xh[(size_t)NTOK * DIMD];   // x hi/lo split
__device__ __nv_bfloat16 g_xl[(size_t)NTOK * DIMD];
__device__ __nv_bfloat16 g_Bph[3072 * 256];           // proj weights, [N][K] bf16 hi/lo
__device__ __nv_bfloat16 g_Bpl[3072 * 256];
__device__ __nv_bfloat16 g_Ohi[(size_t)NTOK * OLD];   // attention output, hi/lo split
__device__ __nv_bfloat16 g_Olo[(size_t)NTOK * OLD];
__device__ __nv_bfloat16 g_Boh[256 * 1024];           // out weights, [N][K] bf16 hi/lo
__device__ __nv_bfloat16 g_Bol[256 * 1024];

// ---------------------------------------------------------------------------
// PTX helpers (compute_103-safe: cp.async + ldmatrix + mma.sync only)
// ---------------------------------------------------------------------------
__device__ __forceinline__ uint32_t smem_to_u32(const void* p) {
    uint32_t a;
    asm("{ .reg .u64 t; cvta.to.shared.u64 t, %1; cvt.u32.u64 %0, t; }" : "=r"(a) : "l"(p));
    return a;
}

#define CP_ASYNC16(dst, src) \
    asm volatile("cp.async.cg.shared.global [%0], [%1], 16;" :: "r"(dst), "l"(src) : "memory")
#define CP_COMMIT() asm volatile("cp.async.commit_group;" ::: "memory")
#define CP_WAIT0()  asm volatile("cp.async.wait_group 0;" ::: "memory")
#define CP_WAIT1()  asm volatile("cp.async.wait_group 1;" ::: "memory")

#define LDMATRIX_X4(d0, d1, d2, d3, addr) \
    asm volatile("ldmatrix.sync.aligned.m8n8.x4.shared.b16 {%0,%1,%2,%3}, [%4];" \
        : "=r"(d0), "=r"(d1), "=r"(d2), "=r"(d3) : "r"(addr))

#define MMA_BF16(c, a0, a1, a2, a3, b0, b1) \
    asm volatile("mma.sync.aligned.m16n8k16.row.col.f32.bf16.bf16.f32 " \
        "{%0,%1,%2,%3}, {%4,%5,%6,%7}, {%8,%9}, {%0,%1,%2,%3};" \
        : "+f"((c)[0]), "+f"((c)[1]), "+f"((c)[2]), "+f"((c)[3]) \
        : "r"(a0), "r"(a1), "r"(a2), "r"(a3), "r"(b0), "r"(b1))

// ---------------------------------------------------------------------------
// Split-bf16 tensor-core GEMM:  C[M x N] = Ah@Bh^T + Al@Bh^T + Ah@Bl^T (+bias)
// A*: [M x K] bf16 row-major (lda). B*: [N x K] bf16 row-major (ldb) = B^T.
// Block tile 128x128, K-chunk 64, 3-stage cp.async pipeline, XOR-8 swizzle.
// 8 warps: warp tile 32(m) x 64(n); per-warp 2x8 m16n8k16 fragments.
// ---------------------------------------------------------------------------
#define STAGES 3
#define CHUNK_BYTES 32768                 // A 16KB + B 16KB
#define GEMM_SMEM (STAGES * CHUNK_BYTES)  // 96 KB

__global__ __launch_bounds__(256)
void gemm_mma(const __nv_bfloat16* __restrict__ Ah, const __nv_bfloat16* __restrict__ Al, int lda,
              const __nv_bfloat16* __restrict__ Bh, const __nv_bfloat16* __restrict__ Bl, int ldb,
              float* __restrict__ C, int ldc, int K,
              const float* __restrict__ bias1, const float* __restrict__ bias2)
{
    extern __shared__ char smem[];
    const uint32_t sb = smem_to_u32(smem);
    const int tid = threadIdx.x;
    const int lane = tid & 31, wid = tid >> 5;
    const int wm = wid & 3, wn = wid >> 2;      // warp grid 4(m) x 2(n)
    const int m0 = blockIdx.y * 128, j0 = blockIdx.x * 128;

    const int NCpp = K >> 6;   // 64-k chunks per pass
    const int NC = 3 * NCpp;

    float acc[2][8][4];
#pragma unroll
    for (int i = 0; i < 2; i++)
#pragma unroll
        for (int j = 0; j < 8; j++)
#pragma unroll
            for (int u = 0; u < 4; u++) acc[i][j][u] = 0.f;

    // ---- async load of one 64-k chunk (A tile + B tile) into stage s ----
    auto load_chunk = [&](int c, int s) {
        const int pass = c / NCpp;
        const int kc = (c - pass * NCpp) << 6;
        const __nv_bfloat16* Ab = (pass == 1) ? Al : Ah;
        const __nv_bfloat16* Bb = (pass == 2) ? Bl : Bh;
        const uint32_t sA = sb + s * CHUNK_BYTES;
        const uint32_t sB = sA + 16384;
#pragma unroll
        for (int i = 0; i < 4; i++) {
            const int id = tid + i * 256;          // 0..1023
            const int row = id & 127, g = id >> 7; // g = 16B group (8 per 128B row)
            const uint32_t dst = row * 128 + (((g ^ (row & 7))) << 4);
            CP_ASYNC16(sA + dst, Ab + (size_t)(m0 + row) * lda + kc + g * 8);
            CP_ASYNC16(sB + dst, Bb + (size_t)(j0 + row) * ldb + kc + g * 8);
        }
        CP_COMMIT();
    };

    // ---- compute one chunk from stage s ----
    auto compute_chunk = [&](int s) {
        const uint32_t sA = sb + s * CHUNK_BYTES;
        const uint32_t sB = sA + 16384;
        const int sub = lane >> 3, r = lane & 7;
#pragma unroll
        for (int ks = 0; ks < 4; ks++) {
            const int kq = ks * 2 + (sub >> 1);
            uint32_t a[2][4];
#pragma unroll
            for (int mi = 0; mi < 2; mi++) {
                const int ml = wm * 32 + mi * 16 + (sub & 1) * 8 + r;
                const uint32_t addr = sA + ml * 128 + (((kq ^ (ml & 7))) << 4);
                LDMATRIX_X4(a[mi][0], a[mi][1], a[mi][2], a[mi][3], addr);
            }
            uint32_t b[4][4];
#pragma unroll
            for (int ni = 0; ni < 4; ni++) {
                const int nl = wn * 64 + ni * 16 + (sub & 1) * 8 + r;
                const uint32_t addr = sB + nl * 128 + (((kq ^ (nl & 7))) << 4);
                LDMATRIX_X4(b[ni][0], b[ni][1], b[ni][2], b[ni][3], addr);
            }
#pragma unroll
            for (int mi = 0; mi < 2; mi++)
#pragma unroll
                for (int ni = 0; ni < 4; ni++) {
                    MMA_BF16(acc[mi][2 * ni + 0], a[mi][0], a[mi][1], a[mi][2], a[mi][3],
                             b[ni][0], b[ni][2]);
                    MMA_BF16(acc[mi][2 * ni + 1], a[mi][0], a[mi][1], a[mi][2], a[mi][3],
                             b[ni][1], b[ni][3]);
                }
        }
    };

    load_chunk(0, 0);
    load_chunk(1, 1);
    for (int c = 0; c < NC; c++) {
        if (c < NC - 1) { CP_WAIT1(); } else { CP_WAIT0(); }
        __syncthreads();
        if (c + 2 < NC) load_chunk(c + 2, (c + 2) % STAGES);
        compute_chunk(c % STAGES);
    }

    // ---- epilogue: direct float2 stores from mma fragments ----
    const int qrow = lane >> 2, qcol = (lane & 3) * 2;
#pragma unroll
    for (int nj = 0; nj < 8; nj++) {
        const int n = j0 + wn * 64 + nj * 8 + qcol;
        float b0 = 0.f, b1 = 0.f;
        if (bias1) {
            b0 = bias1[n] + bias2[n];
            b1 = bias1[n + 1] + bias2[n + 1];
        }
#pragma unroll
        for (int mi = 0; mi < 2; mi++) {
            const int m = m0 + wm * 32 + mi * 16 + qrow;
            float2 v0, v1;
            v0.x = acc[mi][nj][0] + b0; v0.y = acc[mi][nj][1] + b1;
            v1.x = acc[mi][nj][2] + b0; v1.y = acc[mi][nj][3] + b1;
            *(float2*)(C + (size_t)m * ldc + n) = v0;
            *(float2*)(C + (size_t)(m + 8) * ldc + n) = v1;
        }
    }
}

// ---------------------------------------------------------------------------
// fp32 -> bf16 hi/lo split + weight-panel builders
// ---------------------------------------------------------------------------
__global__ void split_f32_kernel(const float* __restrict__ in,
                                 __nv_bfloat16* __restrict__ hi,
                                 __nv_bfloat16* __restrict__ lo, size_t n)
{
    size_t i = (size_t)blockIdx.x * blockDim.x + threadIdx.x;
    const size_t stride = (size_t)gridDim.x * blockDim.x;
    for (; i < n; i += stride) {
        float v = in[i];
        __nv_bfloat16 h = __float2bfloat16(v);
        hi[i] = h;
        lo[i] = __float2bfloat16(v - __bfloat162float(h));
    }
}

__global__ void build_Bp_kernel(const float* __restrict__ wq, const float* __restrict__ wkv,
                                const float* __restrict__ hq, const float* __restrict__ hkv)
{
    const int idx = blockIdx.x * 256 + threadIdx.x;   // k*3072 + n
    const int k = idx / 3072, n = idx - k * 3072;
    float v;
    if (n < 512)       v = wq[k * 512 + n];
    else if (n < 1536) v = wkv[k * 1024 + (n - 512)];
    else if (n < 2048) v = hq[k * 512 + (n - 1536)];
    else               v = hkv[k * 1024 + (n - 2048)];
    __nv_bfloat16 h = __float2bfloat16(v);
    g_Bph[(size_t)n * 256 + k] = h;
    g_Bpl[(size_t)n * 256 + k] = __float2bfloat16(v - __bfloat162float(h));
}

__global__ void build_Bo_kernel(const float* __restrict__ wo, const float* __restrict__ ho)
{
    const int idx = blockIdx.x * 256 + threadIdx.x;   // k*256 + n
    const int k = idx >> 8, n = idx & 255;
    float v = (k < 512) ? wo[k * 256 + n] : ho[(k - 512) * 256 + n];
    __nv_bfloat16 h = __float2bfloat16(v);
    g_Boh[(size_t)n * 1024 + k] = h;
    g_Bol[(size_t)n * 1024 + k] = __float2bfloat16(v - __bfloat162float(h));
}

// ---------------------------------------------------------------------------
// Column-wise attention (w branch). Writes bf16 hi/lo O at cols [0,512).
// ---------------------------------------------------------------------------
#define SQ_LD 129
#define SS_LD 129
#define ATTN_SMEM_FLOATS (2 * 64 * SQ_LD + 128 * SS_LD)

__global__ __launch_bounds__(256) void attn_w_kernel()
{
    extern __shared__ float sm[];
    float* sQ = sm;
    float* sK = sm + 64 * SQ_LD;
    float* sS = sm + 2 * 64 * SQ_LD;
    float* sV = sm;

    const int cw = blockIdx.x;
    const int Hh = blockIdx.y;
    const int tid = threadIdx.x;

    for (int idx = tid * 4; idx < 8192; idx += 1024) {
        int r = idx >> 6, dh = idx & 63;
        const float* p = g_P + (size_t)(r * 256 + cw) * PLD + Hh * 64 + dh;
        float4 q4 = *(const float4*)p;
        float4 k4 = *(const float4*)(p + 512);
        sQ[(dh + 0) * SQ_LD + r] = q4.x; sQ[(dh + 1) * SQ_LD + r] = q4.y;
        sQ[(dh + 2) * SQ_LD + r] = q4.z; sQ[(dh + 3) * SQ_LD + r] = q4.w;
        sK[(dh + 0) * SQ_LD + r] = k4.x; sK[(dh + 1) * SQ_LD + r] = k4.y;
        sK[(dh + 2) * SQ_LD + r] = k4.z; sK[(dh + 3) * SQ_LD + r] = k4.w;
    }
    __syncthreads();

    {
        const int ty = tid >> 4, tx = tid & 15;
        float acc[8][8];
#pragma unroll
        for (int i = 0; i < 8; i++)
#pragma unroll
            for (int j = 0; j < 8; j++) acc[i][j] = 0.f;
#pragma unroll 4
        for (int dh = 0; dh < 64; dh++) {
            float a[8], b[8];
#pragma unroll
            for (int u = 0; u < 8; u++) {
                a[u] = sQ[dh * SQ_LD + ty * 8 + u];
                b[u] = sK[dh * SQ_LD + tx * 8 + u];
            }
#pragma unroll
            for (int i = 0; i < 8; i++)
#pragma unroll
                for (int j = 0; j < 8; j++) acc[i][j] = fmaf(a[i], b[j], acc[i][j]);
        }
#pragma unroll
        for (int i = 0; i < 8; i++)
#pragma unroll
            for (int j = 0; j < 8; j++)
                sS[(ty * 8 + i) * SS_LD + tx * 8 + j] = acc[i][j] * 0.125f;
    }
    __syncthreads();

    for (int idx = tid * 4; idx < 8192; idx += 1024) {
        int r = idx >> 6, dh = idx & 63;
        float4 v4 = *(const float4*)(g_P + (size_t)(r * 256 + cw) * PLD + 1024 + Hh * 64 + dh);
        *(float4*)&sV[r * 64 + dh] = v4;
    }
    if (tid < 128) {
        float* row = sS + tid * SS_LD;
        float m = -1e30f;
        for (int j = 0; j < 128; j++) m = fmaxf(m, row[j]);
        float s = 0.f;
        for (int j = 0; j < 128; j++) { float e = __expf(row[j] - m); row[j] = e; s += e; }
        float inv = 1.f / s;
        for (int j = 0; j < 128; j++) row[j] *= inv;
    }
    __syncthreads();

    {
        const int ty = tid >> 4, tx = tid & 15;
        float o[8][4];
#pragma unroll
        for (int i = 0; i < 8; i++)
#pragma unroll
            for (int j = 0; j < 4; j++) o[i][j] = 0.f;
#pragma unroll 4
        for (int j = 0; j < 128; j++) {
            float4 v = *(const float4*)&sV[j * 64 + tx * 4];
#pragma unroll
            for (int i = 0; i < 8; i++) {
                float a = sS[(ty * 8 + i) * SS_LD + j];
                o[i][0] = fmaf(a, v.x, o[i][0]);
                o[i][1] = fmaf(a, v.y, o[i][1]);
                o[i][2] = fmaf(a, v.z, o[i][2]);
                o[i][3] = fmaf(a, v.w, o[i][3]);
            }
        }
#pragma unroll
        for (int i = 0; i < 8; i++) {
            int r = ty * 8 + i;
            size_t base = (size_t)(r * 256 + cw) * OLD + Hh * 64 + tx * 4;
#pragma unroll
            for (int j = 0; j < 4; j++) {
                float v = o[i][j];
                __nv_bfloat16 h = __float2bfloat16(v);
                g_Ohi[base + j] = h;
                g_Olo[base + j] = __float2bfloat16(v - __bfloat162float(h));
            }
        }
    }
}

// ---------------------------------------------------------------------------
// Tied row attention (h branch)
// ---------------------------------------------------------------------------
__global__ __launch_bounds__(256) void dots_h_kernel()
{
    __shared__ float Ast[64 * 65];
    __shared__ float Bst[64 * 65];
    const int i0 = blockIdx.x * 64;
    const int j0 = blockIdx.y * 64;
    const int Hh = blockIdx.z;
    const int tid = threadIdx.x;
    const int ty = tid >> 4, tx = tid & 15;

    float acc[4][4];
#pragma unroll
    for (int i = 0; i < 4; i++)
#pragma unroll
        for (int j = 0; j < 4; j++) acc[i][j] = 0.f;

    for (int r = 0; r < 128; r++) {
        __syncthreads();
        for (int idx = tid * 4; idx < 4096; idx += 1024) {
            int row = idx >> 6, c = idx & 63;
            float4 a4 = *(const float4*)(g_P + (size_t)(r * 256 + i0 + row) * PLD + 1536 + Hh * 64 + c);
            float4 b4 = *(const float4*)(g_P + (size_t)(r * 256 + j0 + row) * PLD + 2048 + Hh * 64 + c);
            Ast[(c + 0) * 65 + row] = a4.x; Ast[(c + 1) * 65 + row] = a4.y;
            Ast[(c + 2) * 65 + row] = a4.z; Ast[(c + 3) * 65 + row] = a4.w;
            Bst[(c + 0) * 65 + row] = b4.x; Bst[(c + 1) * 65 + row] = b4.y;
            Bst[(c + 2) * 65 + row] = b4.z; Bst[(c + 3) * 65 + row] = b4.w;
        }
        __syncthreads();
#pragma unroll 8
        for (int dh = 0; dh < 64; dh++) {
            float a[4], b[4];
#pragma unroll
            for (int u = 0; u < 4; u++) {
                a[u] = Ast[dh * 65 + ty * 4 + u];
                b[u] = Bst[dh * 65 + tx * 4 + u];
            }
#pragma unroll
            for (int i = 0; i < 4; i++)
#pragma unroll
                for (int j = 0; j < 4; j++) acc[i][j] = fmaf(a[i], b[j], acc[i][j]);
        }
    }
    const float tsc = 0.011048543456039806f;
#pragma unroll
    for (int i = 0; i < 4; i++)
#pragma unroll
        for (int j = 0; j < 4; j++)
            g_Sh[Hh * 65536 + (i0 + ty * 4 + i) * 256 + j0 + tx * 4 + j] = acc[i][j] * tsc;
}

__global__ __launch_bounds__(256) void softmax_h_kernel()
{
    float* p = g_Sh + (size_t)blockIdx.x * 256;
    const int tid = threadIdx.x;
    __shared__ float red[256];
    float v = p[tid];
    red[tid] = v;
    __syncthreads();
#pragma unroll
    for (int s = 128; s > 0; s >>= 1) {
        if (tid < s) red[tid] = fmaxf(red[tid], red[tid + s]);
        __syncthreads();
    }
    float m = red[0];
    __syncthreads();
    float e = __expf(v - m);
    red[tid] = e;
    __syncthreads();
#pragma unroll
    for (int s = 128; s > 0; s >>= 1) {
        if (tid < s) red[tid] += red[tid + s];
        __syncthreads();
    }
    p[tid] = e / red[0];
}

__global__ __launch_bounds__(256) void av_h_kernel()
{
    __shared__ float Ast[64 * 65];
    __shared__ float Vs[64 * 64];
    const int r  = blockIdx.x;
    const int i0 = blockIdx.y * 64;
    const int Hh = blockIdx.z;
    const int tid = threadIdx.x;
    const int ty = tid >> 4, tx = tid & 15;

    float acc[4][4];
#pragma unroll
    for (int i = 0; i < 4; i++)
#pragma unroll
        for (int j = 0; j < 4; j++) acc[i][j] = 0.f;

    for (int jc = 0; jc < 256; jc += 64) {
        __syncthreads();
        for (int idx = tid * 4; idx < 4096; idx += 1024) {
            int row = idx >> 6, c = idx & 63;
            float4 a4 = *(const float4*)(g_Sh + Hh * 65536 + (i0 + row) * 256 + jc + c);
            Ast[(c + 0) * 65 + row] = a4.x; Ast[(c + 1) * 65 + row] = a4.y;
            Ast[(c + 2) * 65 + row] = a4.z; Ast[(c + 3) * 65 + row] = a4.w;
            float4 v4 = *(const float4*)(g_P + (size_t)(r * 256 + jc + row) * PLD + 2560 + Hh * 64 + c);
            *(float4*)&Vs[row * 64 + c] = v4;
        }
        __syncthreads();
#pragma unroll 8
        for (int jj = 0; jj < 64; jj++) {
            float a[4];
#pragma unroll
            for (int u = 0; u < 4; u++) a[u] = Ast[jj * 65 + ty * 4 + u];
            float4 bv = *(const float4*)&Vs[jj * 64 + tx * 4];
#pragma unroll
            for (int i = 0; i < 4; i++) {
                acc[i][0] = fmaf(a[i], bv.x, acc[i][0]);
                acc[i][1] = fmaf(a[i], bv.y, acc[i][1]);
                acc[i][2] = fmaf(a[i], bv.z, acc[i][2]);
                acc[i][3] = fmaf(a[i], bv.w, acc[i][3]);
            }
        }
    }
#pragma unroll
    for (int i = 0; i < 4; i++) {
        int ii = i0 + ty * 4 + i;
        size_t base = (size_t)(r * 256 + ii) * OLD + 512 + Hh * 64 + tx * 4;
#pragma unroll
        for (int j = 0; j < 4; j++) {
            float v = acc[i][j];
            __nv_bfloat16 h = __float2bfloat16(v);
            g_Ohi[base + j] = h;
            g_Olo[base + j] = __float2bfloat16(v - __bfloat162float(h));
        }
    }
}

// ---------------------------------------------------------------------------
extern "C" void kernel_launch(void* const* d_in, const int* in_sizes, int n_in,
                              void* d_out, int out_size)
{
    const float* x      = (const float*)d_in[0];
    const float* wq_w   = (const float*)d_in[1];
    const float* wkv_w  = (const float*)d_in[2];
    const float* wout_w = (const float*)d_in[3];
    const float* wout_b = (const float*)d_in[4];
    const float* hq_w   = (const float*)d_in[5];
    const float* hkv_w  = (const float*)d_in[6];
    const float* hout_w = (const float*)d_in[7];
    const float* hout_b = (const float*)d_in[8];
    float* out = (float*)d_out;

    float *P;
    __nv_bfloat16 *xh, *xl, *Bph, *Bpl, *Ohi, *Olo, *Boh, *Bol;
    cudaGetSymbolAddress((void**)&P, g_P);
    cudaGetSymbolAddress((void**)&xh, g_xh);
    cudaGetSymbolAddress((void**)&xl, g_xl);
    cudaGetSymbolAddress((void**)&Bph, g_Bph);
    cudaGetSymbolAddress((void**)&Bpl, g_Bpl);
    cudaGetSymbolAddress((void**)&Ohi, g_Ohi);
    cudaGetSymbolAddress((void**)&Olo, g_Olo);
    cudaGetSymbolAddress((void**)&Boh, g_Boh);
    cudaGetSymbolAddress((void**)&Bol, g_Bol);

    cudaFuncSetAttribute(gemm_mma, cudaFuncAttributeMaxDynamicSharedMemorySize, GEMM_SMEM);
    cudaFuncSetAttribute(attn_w_kernel, cudaFuncAttributeMaxDynamicSharedMemorySize,
                         ATTN_SMEM_FLOATS * (int)sizeof(float));

    // 1) Split inputs to bf16 hi/lo + build transposed weight panels
    split_f32_kernel<<<4096, 256>>>(x, xh, xl, (size_t)NTOK * DIMD);
    build_Bp_kernel<<<3072, 256>>>(wq_w, wkv_w, hq_w, hkv_w);
    build_Bo_kernel<<<1024, 256>>>(wout_w, hout_w);

    // 2) Projections via mma.sync: P = x @ [wq|wkv|hq|hkv]  (M=32768, N=3072, K=256)
    gemm_mma<<<dim3(24, 256), 256, GEMM_SMEM>>>(xh, xl, DIMD, Bph, Bpl, DIMD,
                                                P, PLD, DIMD, nullptr, nullptr);

    // 3) Column-wise attention (w branch) -> O cols [0,512)
    attn_w_kernel<<<dim3(256, 8), 256, ATTN_SMEM_FLOATS * sizeof(float)>>>();

    // 4) Tied row attention (h branch) -> O cols [512,1024)
    dots_h_kernel<<<dim3(4, 4, 8), 256>>>();
    softmax_h_kernel<<<2048, 256>>>();
    av_h_kernel<<<dim3(128, 4, 8), 256>>>();

    // 5) out = O @ [wout;hout] + biases via mma.sync (M=32768, N=256, K=1024)
    gemm_mma<<<dim3(2, 256), 256, GEMM_SMEM>>>(Ohi, Olo, OLD, Boh, Bol, 1024,
                                               out, DIMD, 1024, wout_b, hout_b);
}

// round 4
// speedup vs baseline: 1.8918x; 1.4900x over previous
#include <cuda_runtime.h>
#include <cuda_bf16.h>
#include <cstdint>

#define NTOK  32768
#define DIMD  256
#define HEADS 8
#define MSAH  128
#define MSAW  256
#define PLD   3072   // P cols: [wq(512) | wk(512)@512 | wv(512)@1024 | hq(512)@1536 | hk@2048 | hv@2560]
#define OLD   1024   // O cols: [Ow(512) | Oh(512)]
#define TSC   0.011048543456039806f  // 64^-0.5 * 128^-0.5

// ---------------------------------------------------------------------------
// Scratch
// ---------------------------------------------------------------------------
__device__ __nv_bfloat16 g_Ph[(size_t)NTOK * PLD];    // projections hi (201MB)
__device__ __nv_bfloat16 g_Pl[(size_t)NTOK * PLD];    // projections lo
__device__ float g_Shp[4 * HEADS * 256 * 256];        // tied-attn logit partials (8MB)
__device__ __nv_bfloat16 g_Shh[HEADS * 256 * 256];    // tied-attn probs hi/lo
__device__ __nv_bfloat16 g_Shl[HEADS * 256 * 256];
__device__ __nv_bfloat16 g_xh[(size_t)NTOK * DIMD];
__device__ __nv_bfloat16 g_xl[(size_t)NTOK * DIMD];
__device__ __nv_bfloat16 g_Bph[3072 * 256];
__device__ __nv_bfloat16 g_Bpl[3072 * 256];
__device__ __nv_bfloat16 g_Ohi[(size_t)NTOK * OLD];
__device__ __nv_bfloat16 g_Olo[(size_t)NTOK * OLD];
__device__ __nv_bfloat16 g_Boh[256 * 1024];
__device__ __nv_bfloat16 g_Bol[256 * 1024];

// ---------------------------------------------------------------------------
// PTX helpers (compute_103-safe)
// ---------------------------------------------------------------------------
__device__ __forceinline__ uint32_t smem_to_u32(const void* p) {
    uint32_t a;
    asm("{ .reg .u64 t; cvta.to.shared.u64 t, %1; cvt.u32.u64 %0, t; }" : "=r"(a) : "l"(p));
    return a;
}
#define CP_ASYNC16(dst, src) \
    asm volatile("cp.async.cg.shared.global [%0], [%1], 16;" :: "r"(dst), "l"(src) : "memory")
#define CP_COMMIT() asm volatile("cp.async.commit_group;" ::: "memory")
#define CP_WAIT0()  asm volatile("cp.async.wait_group 0;" ::: "memory")
#define CP_WAIT1()  asm volatile("cp.async.wait_group 1;" ::: "memory")

#define LDMATRIX_X4(d0, d1, d2, d3, addr) \
    asm volatile("ldmatrix.sync.aligned.m8n8.x4.shared.b16 {%0,%1,%2,%3}, [%4];" \
        : "=r"(d0), "=r"(d1), "=r"(d2), "=r"(d3) : "r"(addr))
#define LDMATRIX_X4_T(d0, d1, d2, d3, addr) \
    asm volatile("ldmatrix.sync.aligned.m8n8.x4.trans.shared.b16 {%0,%1,%2,%3}, [%4];" \
        : "=r"(d0), "=r"(d1), "=r"(d2), "=r"(d3) : "r"(addr))

#define MMA_BF16(c, a0, a1, a2, a3, b0, b1) \
    asm volatile("mma.sync.aligned.m16n8k16.row.col.f32.bf16.bf16.f32 " \
        "{%0,%1,%2,%3}, {%4,%5,%6,%7}, {%8,%9}, {%0,%1,%2,%3};" \
        : "+f"((c)[0]), "+f"((c)[1]), "+f"((c)[2]), "+f"((c)[3]) \
        : "r"(a0), "r"(a1), "r"(a2), "r"(a3), "r"(b0), "r"(b1))

__device__ __forceinline__ uint32_t pack_bf16x2(float lo, float hi) {
    __nv_bfloat162 t = __floats2bfloat162_rn(lo, hi);
    return *reinterpret_cast<uint32_t*>(&t);
}
__device__ __forceinline__ void split2_store(__nv_bfloat16* hi, __nv_bfloat16* lo,
                                             float a, float b) {
    __nv_bfloat16 ha = __float2bfloat16(a), hb = __float2bfloat16(b);
    __nv_bfloat162 h; h.x = ha; h.y = hb;
    *reinterpret_cast<__nv_bfloat162*>(hi) = h;
    __nv_bfloat162 l;
    l.x = __float2bfloat16(a - __bfloat162float(ha));
    l.y = __float2bfloat16(b - __bfloat162float(hb));
    *reinterpret_cast<__nv_bfloat162*>(lo) = l;
}

// ---------------------------------------------------------------------------
// Shared 128x128 tile compute: one 32-k chunk (hi|lo packed per 128B row).
// Stage layout: rows of 128B; granules 0-3 = hi k0..31, granules 4-7 = lo.
// Warp grid 4(m) x 2(n); warp tile 32x64; 3 MMA combos per fragment pair.
// ---------------------------------------------------------------------------
__device__ __forceinline__ void compute_chunk128(uint32_t sAst, uint32_t sBst,
                                                 int lane, int wm, int wn,
                                                 float acc[2][8][4])
{
#pragma unroll
    for (int kb = 0; kb < 2; kb++) {
        const int lg = kb * 2 + (lane >> 4);
        uint32_t ah[2][4], al[2][4];
#pragma unroll
        for (int mi = 0; mi < 2; mi++) {
            const int row = wm * 32 + mi * 16 + (lane & 15);
            LDMATRIX_X4(ah[mi][0], ah[mi][1], ah[mi][2], ah[mi][3],
                        sAst + row * 128 + (((lg) ^ (row & 7)) << 4));
            LDMATRIX_X4(al[mi][0], al[mi][1], al[mi][2], al[mi][3],
                        sAst + row * 128 + (((lg + 4) ^ (row & 7)) << 4));
        }
#pragma unroll
        for (int nf = 0; nf < 4; nf++) {
            const int row = wn * 64 + nf * 16 + (lane & 15);
            uint32_t b0, b1, b2, b3, c0, c1, c2, c3;
            LDMATRIX_X4(b0, b1, b2, b3, sBst + row * 128 + (((lg) ^ (row & 7)) << 4));
            LDMATRIX_X4(c0, c1, c2, c3, sBst + row * 128 + (((lg + 4) ^ (row & 7)) << 4));
#pragma unroll
            for (int mi = 0; mi < 2; mi++) {
                MMA_BF16(acc[mi][2 * nf],     ah[mi][0], ah[mi][1], ah[mi][2], ah[mi][3], b0, b2);
                MMA_BF16(acc[mi][2 * nf + 1], ah[mi][0], ah[mi][1], ah[mi][2], ah[mi][3], b1, b3);
                MMA_BF16(acc[mi][2 * nf],     al[mi][0], al[mi][1], al[mi][2], al[mi][3], b0, b2);
                MMA_BF16(acc[mi][2 * nf + 1], al[mi][0], al[mi][1], al[mi][2], al[mi][3], b1, b3);
                MMA_BF16(acc[mi][2 * nf],     ah[mi][0], ah[mi][1], ah[mi][2], ah[mi][3], c0, c2);
                MMA_BF16(acc[mi][2 * nf + 1], ah[mi][0], ah[mi][1], ah[mi][2], ah[mi][3], c1, c3);
            }
        }
    }
}

// ---------------------------------------------------------------------------
// Fused hi/lo split-bf16 GEMM:  C = (Ah+Al)@(Bh+Bl)^T - Al@Bl^T  (+bias)
// Epilogue: C fp32 (+bias1+bias2) if C != nullptr, else bf16 hi/lo split.
// ---------------------------------------------------------------------------
#define GEMM_SMEM (3 * 32768)   // 96 KB (3 stages x (A 16KB + B 16KB))

__global__ __launch_bounds__(256)
void gemm_mma(const __nv_bfloat16* __restrict__ Ah, const __nv_bfloat16* __restrict__ Al, int lda,
              const __nv_bfloat16* __restrict__ Bh, const __nv_bfloat16* __restrict__ Bl, int ldb,
              float* __restrict__ C,
              __nv_bfloat16* __restrict__ Chi, __nv_bfloat16* __restrict__ Clo,
              int ldc, int K,
              const float* __restrict__ bias1, const float* __restrict__ bias2)
{
    extern __shared__ char smem[];
    const uint32_t sb = smem_to_u32(smem);
    const int tid = threadIdx.x, lane = tid & 31, wid = tid >> 5;
    const int wm = wid & 3, wn = wid >> 2;
    const int m0 = blockIdx.y * 128, j0 = blockIdx.x * 128;
    const int NC = K >> 5;

    float acc[2][8][4];
#pragma unroll
    for (int i = 0; i < 2; i++)
#pragma unroll
        for (int j = 0; j < 8; j++)
#pragma unroll
            for (int u = 0; u < 4; u++) acc[i][j][u] = 0.f;

    auto load_chunk = [&](int c, int s) {
        const int kc = c << 5;
        const uint32_t sA = sb + s * 32768, sB = sA + 16384;
#pragma unroll
        for (int i = 0; i < 4; i++) {
            const int id = tid + i * 256;
            const int row = id & 127, g = id >> 7;
            const uint32_t off = row * 128 + ((g ^ (row & 7)) << 4);
            const __nv_bfloat16* Asrc = (g < 4) ? Ah : Al;
            const __nv_bfloat16* Bsrc = (g < 4) ? Bh : Bl;
            CP_ASYNC16(sA + off, Asrc + (size_t)(m0 + row) * lda + kc + (g & 3) * 8);
            CP_ASYNC16(sB + off, Bsrc + (size_t)(j0 + row) * ldb + kc + (g & 3) * 8);
        }
        CP_COMMIT();
    };

    load_chunk(0, 0);
    load_chunk(1, 1);
    for (int c = 0; c < NC; c++) {
        if (c < NC - 1) { CP_WAIT1(); } else { CP_WAIT0(); }
        __syncthreads();
        if (c + 2 < NC) load_chunk(c + 2, (c + 2) % 3);
        const uint32_t sA = sb + (c % 3) * 32768;
        compute_chunk128(sA, sA + 16384, lane, wm, wn, acc);
    }

    const int qrow = lane >> 2, qcol2 = (lane & 3) * 2;
    if (C) {
#pragma unroll
        for (int nj = 0; nj < 8; nj++) {
            const int n = j0 + wn * 64 + nj * 8 + qcol2;
            float b0 = 0.f, b1 = 0.f;
            if (bias1) { b0 = bias1[n] + bias2[n]; b1 = bias1[n + 1] + bias2[n + 1]; }
#pragma unroll
            for (int mi = 0; mi < 2; mi++) {
                const int m = m0 + wm * 32 + mi * 16 + qrow;
                float2 v0, v1;
                v0.x = acc[mi][nj][0] + b0; v0.y = acc[mi][nj][1] + b1;
                v1.x = acc[mi][nj][2] + b0; v1.y = acc[mi][nj][3] + b1;
                *(float2*)(C + (size_t)m * ldc + n) = v0;
                *(float2*)(C + (size_t)(m + 8) * ldc + n) = v1;
            }
        }
    } else {
#pragma unroll
        for (int nj = 0; nj < 8; nj++) {
            const int n = j0 + wn * 64 + nj * 8 + qcol2;
#pragma unroll
            for (int mi = 0; mi < 2; mi++) {
                const int m = m0 + wm * 32 + mi * 16 + qrow;
                split2_store(Chi + (size_t)m * ldc + n, Clo + (size_t)m * ldc + n,
                             acc[mi][nj][0], acc[mi][nj][1]);
                split2_store(Chi + (size_t)(m + 8) * ldc + n, Clo + (size_t)(m + 8) * ldc + n,
                             acc[mi][nj][2], acc[mi][nj][3]);
            }
        }
    }
}

// ---------------------------------------------------------------------------
// splitters / weight-panel builders
// ---------------------------------------------------------------------------
__global__ void split_f32_kernel(const float* __restrict__ in,
                                 __nv_bfloat16* __restrict__ hi,
                                 __nv_bfloat16* __restrict__ lo, size_t n)
{
    size_t i = (size_t)blockIdx.x * blockDim.x + threadIdx.x;
    const size_t stride = (size_t)gridDim.x * blockDim.x;
    for (; i < n; i += stride) {
        float v = in[i];
        __nv_bfloat16 h = __float2bfloat16(v);
        hi[i] = h;
        lo[i] = __float2bfloat16(v - __bfloat162float(h));
    }
}
__global__ void build_Bp_kernel(const float* __restrict__ wq, const float* __restrict__ wkv,
                                const float* __restrict__ hq, const float* __restrict__ hkv)
{
    const int idx = blockIdx.x * 256 + threadIdx.x;   // k*3072 + n
    const int k = idx / 3072, n = idx - k * 3072;
    float v;
    if (n < 512)       v = wq[k * 512 + n];
    else if (n < 1536) v = wkv[k * 1024 + (n - 512)];
    else if (n < 2048) v = hq[k * 512 + (n - 1536)];
    else               v = hkv[k * 1024 + (n - 2048)];
    __nv_bfloat16 h = __float2bfloat16(v);
    g_Bph[(size_t)n * 256 + k] = h;
    g_Bpl[(size_t)n * 256 + k] = __float2bfloat16(v - __bfloat162float(h));
}
__global__ void build_Bo_kernel(const float* __restrict__ wo, const float* __restrict__ ho)
{
    const int idx = blockIdx.x * 256 + threadIdx.x;   // k*256 + n
    const int k = idx >> 8, n = idx & 255;
    float v = (k < 512) ? wo[k * 256 + n] : ho[(k - 512) * 256 + n];
    __nv_bfloat16 h = __float2bfloat16(v);
    g_Boh[(size_t)n * 1024 + k] = h;
    g_Bol[(size_t)n * 1024 + k] = __float2bfloat16(v - __bfloat162float(h));
}

// ---------------------------------------------------------------------------
// Column attention (w branch), tensor cores. One block per (cw, H).
// smem tiles (each 128 rows x 64 bf16 = 16KB): Qh Ql Kh Kl Vh Vl.
// Warp tile 16(m)x128(n) -> softmax fully in registers (quad shuffles).
// ---------------------------------------------------------------------------
#define ATTNW_SMEM (6 * 16384)   // 96 KB

__global__ __launch_bounds__(256) void attn_w_mma()
{
    extern __shared__ char smem[];
    const uint32_t sb = smem_to_u32(smem);
    const int cw = blockIdx.x, H = blockIdx.y;
    const int tid = threadIdx.x, lane = tid & 31, wid = tid >> 5;

    // load 6 tiles
#pragma unroll
    for (int t = 0; t < 6; t++) {
        const __nv_bfloat16* src = (t & 1) ? g_Pl : g_Ph;
        const int coff = (t >> 1) * 512 + H * 64;
#pragma unroll
        for (int i = 0; i < 4; i++) {
            const int id = tid + i * 256;
            const int row = id & 127, g = id >> 7;
            CP_ASYNC16(sb + t * 16384 + row * 128 + ((g ^ (row & 7)) << 4),
                       src + (size_t)(row * 256 + cw) * PLD + coff + g * 8);
        }
    }
    CP_COMMIT(); CP_WAIT0();
    __syncthreads();

    const uint32_t sQh = sb, sQl = sb + 16384, sKh = sb + 32768,
                   sKl = sb + 49152, sVh = sb + 65536, sVl = sb + 81920;
    const int i0w = wid * 16;

    // S = scale * Q K^T  (M=16 rows/warp, N=128, K=64)
    float acc[16][4];
#pragma unroll
    for (int i = 0; i < 16; i++)
#pragma unroll
        for (int u = 0; u < 4; u++) acc[i][u] = 0.f;

#pragma unroll
    for (int kb = 0; kb < 4; kb++) {
        const int lg = kb * 2 + (lane >> 4);
        const int ar = i0w + (lane & 15);
        const uint32_t aoff = ar * 128 + ((lg ^ (ar & 7)) << 4);
        uint32_t ah[4], al[4];
        LDMATRIX_X4(ah[0], ah[1], ah[2], ah[3], sQh + aoff);
        LDMATRIX_X4(al[0], al[1], al[2], al[3], sQl + aoff);
#pragma unroll
        for (int nf = 0; nf < 8; nf++) {
            const int br = nf * 16 + (lane & 15);
            const uint32_t boff = br * 128 + ((lg ^ (br & 7)) << 4);
            uint32_t b0, b1, b2, b3, c0, c1, c2, c3;
            LDMATRIX_X4(b0, b1, b2, b3, sKh + boff);
            LDMATRIX_X4(c0, c1, c2, c3, sKl + boff);
            MMA_BF16(acc[2 * nf],     ah[0], ah[1], ah[2], ah[3], b0, b2);
            MMA_BF16(acc[2 * nf + 1], ah[0], ah[1], ah[2], ah[3], b1, b3);
            MMA_BF16(acc[2 * nf],     al[0], al[1], al[2], al[3], b0, b2);
            MMA_BF16(acc[2 * nf + 1], al[0], al[1], al[2], al[3], b1, b3);
            MMA_BF16(acc[2 * nf],     ah[0], ah[1], ah[2], ah[3], c0, c2);
            MMA_BF16(acc[2 * nf + 1], ah[0], ah[1], ah[2], ah[3], c1, c3);
        }
    }

    // softmax in registers: rows qrow, qrow+8 of warp's 16
    float mx0 = -1e30f, mx1 = -1e30f;
#pragma unroll
    for (int ni = 0; ni < 16; ni++) {
        acc[ni][0] *= 0.125f; acc[ni][1] *= 0.125f;
        acc[ni][2] *= 0.125f; acc[ni][3] *= 0.125f;
        mx0 = fmaxf(mx0, fmaxf(acc[ni][0], acc[ni][1]));
        mx1 = fmaxf(mx1, fmaxf(acc[ni][2], acc[ni][3]));
    }
    mx0 = fmaxf(mx0, __shfl_xor_sync(0xffffffffu, mx0, 1));
    mx0 = fmaxf(mx0, __shfl_xor_sync(0xffffffffu, mx0, 2));
    mx1 = fmaxf(mx1, __shfl_xor_sync(0xffffffffu, mx1, 1));
    mx1 = fmaxf(mx1, __shfl_xor_sync(0xffffffffu, mx1, 2));
    float s0 = 0.f, s1 = 0.f;
#pragma unroll
    for (int ni = 0; ni < 16; ni++) {
        float e;
        e = __expf(acc[ni][0] - mx0); acc[ni][0] = e; s0 += e;
        e = __expf(acc[ni][1] - mx0); acc[ni][1] = e; s0 += e;
        e = __expf(acc[ni][2] - mx1); acc[ni][2] = e; s1 += e;
        e = __expf(acc[ni][3] - mx1); acc[ni][3] = e; s1 += e;
    }
    s0 += __shfl_xor_sync(0xffffffffu, s0, 1);
    s0 += __shfl_xor_sync(0xffffffffu, s0, 2);
    s1 += __shfl_xor_sync(0xffffffffu, s1, 1);
    s1 += __shfl_xor_sync(0xffffffffu, s1, 2);
    const float inv0 = 1.f / s0, inv1 = 1.f / s1;

    // pack probs into A-fragments (hi + lo)
    uint32_t aph[8][4], apl[8][4];
#pragma unroll
    for (int kb = 0; kb < 8; kb++) {
        const int n0 = 2 * kb, n1 = n0 + 1;
        float p[8];
        p[0] = acc[n0][0] * inv0; p[1] = acc[n0][1] * inv0;
        p[2] = acc[n0][2] * inv1; p[3] = acc[n0][3] * inv1;
        p[4] = acc[n1][0] * inv0; p[5] = acc[n1][1] * inv0;
        p[6] = acc[n1][2] * inv1; p[7] = acc[n1][3] * inv1;
#pragma unroll
        for (int u = 0; u < 4; u++) {
            float a = p[2 * u], b = p[2 * u + 1];
            __nv_bfloat16 ha = __float2bfloat16(a), hb = __float2bfloat16(b);
            aph[kb][u] = pack_bf16x2(__bfloat162float(ha), __bfloat162float(hb));
            // re-pack exact hi halves then residuals:
            __nv_bfloat162 hh; hh.x = ha; hh.y = hb;
            aph[kb][u] = *reinterpret_cast<uint32_t*>(&hh);
            apl[kb][u] = pack_bf16x2(a - __bfloat162float(ha), b - __bfloat162float(hb));
        }
    }

    // O = P V  (K=128 over j, N=64)
    float acco[8][4];
#pragma unroll
    for (int i = 0; i < 8; i++)
#pragma unroll
        for (int u = 0; u < 4; u++) acco[i][u] = 0.f;

#pragma unroll
    for (int kb = 0; kb < 8; kb++) {
        const int jrow = kb * 16 + ((lane >> 3) & 1) * 8 + (lane & 7);
#pragma unroll
        for (int nfp = 0; nfp < 4; nfp++) {
            const int ncol = nfp * 16 + (lane >> 4) * 8;
            const uint32_t voff = jrow * 128 + ((((ncol >> 3) ^ (jrow & 7))) << 4);
            uint32_t b0, b1, b2, b3, c0, c1, c2, c3;
            LDMATRIX_X4_T(b0, b1, b2, b3, sVh + voff);
            LDMATRIX_X4_T(c0, c1, c2, c3, sVl + voff);
            MMA_BF16(acco[2 * nfp],     aph[kb][0], aph[kb][1], aph[kb][2], aph[kb][3], b0, b1);
            MMA_BF16(acco[2 * nfp + 1], aph[kb][0], aph[kb][1], aph[kb][2], aph[kb][3], b2, b3);
            MMA_BF16(acco[2 * nfp],     apl[kb][0], apl[kb][1], apl[kb][2], apl[kb][3], b0, b1);
            MMA_BF16(acco[2 * nfp + 1], apl[kb][0], apl[kb][1], apl[kb][2], apl[kb][3], b2, b3);
            MMA_BF16(acco[2 * nfp],     aph[kb][0], aph[kb][1], aph[kb][2], aph[kb][3], c0, c1);
            MMA_BF16(acco[2 * nfp + 1], aph[kb][0], aph[kb][1], aph[kb][2], aph[kb][3], c2, c3);
        }
    }

    // write O (cols [0,512))
    const int r0 = i0w + (lane >> 2), r1 = r0 + 8;
#pragma unroll
    for (int nf = 0; nf < 8; nf++) {
        const int c = H * 64 + nf * 8 + (lane & 3) * 2;
        const size_t t0 = (size_t)(r0 * 256 + cw) * OLD + c;
        const size_t t1 = (size_t)(r1 * 256 + cw) * OLD + c;
        split2_store(g_Ohi + t0, g_Olo + t0, acco[nf][0], acco[nf][1]);
        split2_store(g_Ohi + t1, g_Olo + t1, acco[nf][2], acco[nf][3]);
    }
}

// ---------------------------------------------------------------------------
// Tied row attention dots (h branch): S_H[i,j] partials, split-K over r.
// Grid: x = ij tile (4), y = H (8), z = split (4). 128x128 tile per block.
// ---------------------------------------------------------------------------
#define DOTS_SMEM (3 * 32768)

__global__ __launch_bounds__(256) void dots_h_mma()
{
    extern __shared__ char smem[];
    const uint32_t sb = smem_to_u32(smem);
    const int tid = threadIdx.x, lane = tid & 31, wid = tid >> 5;
    const int wm = wid & 3, wn = wid >> 2;
    const int i0 = (blockIdx.x & 1) * 128, j0 = (blockIdx.x >> 1) * 128;
    const int H = blockIdx.y, sp = blockIdx.z;
    const int rbase = sp * 32;
    const int NC = 64;   // 32 r x 2 dh-halves

    float acc[2][8][4];
#pragma unroll
    for (int i = 0; i < 2; i++)
#pragma unroll
        for (int j = 0; j < 8; j++)
#pragma unroll
            for (int u = 0; u < 4; u++) acc[i][j][u] = 0.f;

    auto load_chunk = [&](int c, int s) {
        const int r = rbase + (c >> 1), dhc = (c & 1) * 32;
        const size_t abase = ((size_t)(r * 256 + i0)) * PLD + 1536 + H * 64 + dhc;
        const size_t bbase = ((size_t)(r * 256 + j0)) * PLD + 2048 + H * 64 + dhc;
        const uint32_t sA = sb + s * 32768, sB = sA + 16384;
#pragma unroll
        for (int i = 0; i < 4; i++) {
            const int id = tid + i * 256;
            const int row = id & 127, g = id >> 7;
            const uint32_t off = row * 128 + ((g ^ (row & 7)) << 4);
            const __nv_bfloat16* src = (g < 4) ? g_Ph : g_Pl;
            CP_ASYNC16(sA + off, src + abase + (size_t)row * PLD + (g & 3) * 8);
            CP_ASYNC16(sB + off, src + bbase + (size_t)row * PLD + (g & 3) * 8);
        }
        CP_COMMIT();
    };

    load_chunk(0, 0);
    load_chunk(1, 1);
    for (int c = 0; c < NC; c++) {
        if (c < NC - 1) { CP_WAIT1(); } else { CP_WAIT0(); }
        __syncthreads();
        if (c + 2 < NC) load_chunk(c + 2, (c + 2) % 3);
        const uint32_t sA = sb + (c % 3) * 32768;
        compute_chunk128(sA, sA + 16384, lane, wm, wn, acc);
    }

    float* Cp = g_Shp + (size_t)sp * 524288 + (size_t)H * 65536;
    const int qrow = lane >> 2, qcol2 = (lane & 3) * 2;
#pragma unroll
    for (int nj = 0; nj < 8; nj++) {
        const int n = j0 + wn * 64 + nj * 8 + qcol2;
#pragma unroll
        for (int mi = 0; mi < 2; mi++) {
            const int m = i0 + wm * 32 + mi * 16 + qrow;
            float2 v0, v1;
            v0.x = acc[mi][nj][0]; v0.y = acc[mi][nj][1];
            v1.x = acc[mi][nj][2]; v1.y = acc[mi][nj][3];
            *(float2*)(Cp + m * 256 + n) = v0;
            *(float2*)(Cp + (m + 8) * 256 + n) = v1;
        }
    }
}

// Sum 4 partials, scale, softmax over 256, emit bf16 hi/lo probs.
__global__ __launch_bounds__(256) void softmax_h_kernel()
{
    const size_t base = (size_t)blockIdx.x * 256;
    const int t = threadIdx.x;
    __shared__ float red[256];
    float v = (g_Shp[base + t] + g_Shp[524288 + base + t] +
               g_Shp[2 * 524288 + base + t] + g_Shp[3 * 524288 + base + t]) * TSC;
    red[t] = v;
    __syncthreads();
#pragma unroll
    for (int s = 128; s > 0; s >>= 1) {
        if (t < s) red[t] = fmaxf(red[t], red[t + s]);
        __syncthreads();
    }
    const float m = red[0];
    __syncthreads();
    const float e = __expf(v - m);
    red[t] = e;
    __syncthreads();
#pragma unroll
    for (int s = 128; s > 0; s >>= 1) {
        if (t < s) red[t] += red[t + s];
        __syncthreads();
    }
    const float p = e / red[0];
    const __nv_bfloat16 h = __float2bfloat16(p);
    g_Shh[base + t] = h;
    g_Shl[base + t] = __float2bfloat16(p - __bfloat162float(h));
}

// ---------------------------------------------------------------------------
// Tied row attention AV: O_h[r,i,dh] = sum_j P_H[i,j] V[r,j,dh].
// Grid (r=128, H=8). Block: M=256(i) x N=64(dh), K=256(j), chunks of 32.
// Warp m-tiles of 32; B (V) via ldmatrix.trans. 2-stage pipeline.
// ---------------------------------------------------------------------------
#define AV_SMEM (2 * 40960)   // 2 stages x (A 32KB + V 8KB)

__global__ __launch_bounds__(256) void av_h_mma()
{
    extern __shared__ char smem[];
    const uint32_t sb = smem_to_u32(smem);
    const int r = blockIdx.x, H = blockIdx.y;
    const int tid = threadIdx.x, lane = tid & 31, wid = tid >> 5;
    const int i0w = wid * 32;
    const int NC = 8;

    float acc[2][8][4];
#pragma unroll
    for (int i = 0; i < 2; i++)
#pragma unroll
        for (int j = 0; j < 8; j++)
#pragma unroll
            for (int u = 0; u < 4; u++) acc[i][j][u] = 0.f;

    auto load_chunk = [&](int c, int s) {
        const int jc = c << 5;
        const uint32_t sA = sb + s * 40960, sV = sA + 32768;
#pragma unroll
        for (int i = 0; i < 8; i++) {                 // probs: 256 rows x 8 granules
            const int id = tid + i * 256;
            const int row = id & 255, g = id >> 8;
            const __nv_bfloat16* src = (g < 4) ? g_Shh : g_Shl;
            CP_ASYNC16(sA + row * 128 + ((g ^ (row & 7)) << 4),
                       src + (size_t)H * 65536 + row * 256 + jc + (g & 3) * 8);
        }
#pragma unroll
        for (int i = 0; i < 2; i++) {                 // V: 32 rows x 8 granules x {h,l}
            const int id = tid + i * 256;
            const int jrow = id & 31, g = (id >> 5) & 7, half = id >> 8;
            const __nv_bfloat16* src = half ? g_Pl : g_Ph;
            CP_ASYNC16(sV + half * 4096 + jrow * 128 + ((g ^ (jrow & 7)) << 4),
                       src + (size_t)(r * 256 + jc + jrow) * PLD + 2560 + H * 64 + g * 8);
        }
        CP_COMMIT();
    };

    load_chunk(0, 0);
    load_chunk(1, 1);
    for (int c = 0; c < NC; c++) {
        if (c + 1 < NC) { CP_WAIT1(); } else { CP_WAIT0(); }
        __syncthreads();
        const uint32_t sA = sb + (c & 1) * 40960, sV = sA + 32768;
#pragma unroll
        for (int kb = 0; kb < 2; kb++) {
            const int lg = kb * 2 + (lane >> 4);
            uint32_t ah[2][4], al[2][4];
#pragma unroll
            for (int mi = 0; mi < 2; mi++) {
                const int row = i0w + mi * 16 + (lane & 15);
                LDMATRIX_X4(ah[mi][0], ah[mi][1], ah[mi][2], ah[mi][3],
                            sA + row * 128 + ((lg ^ (row & 7)) << 4));
                LDMATRIX_X4(al[mi][0], al[mi][1], al[mi][2], al[mi][3],
                            sA + row * 128 + (((lg + 4) ^ (row & 7)) << 4));
            }
            const int jrow = kb * 16 + ((lane >> 3) & 1) * 8 + (lane & 7);
#pragma unroll
            for (int nfp = 0; nfp < 4; nfp++) {
                const int ncol = nfp * 16 + (lane >> 4) * 8;
                const uint32_t voff = jrow * 128 + ((((ncol >> 3) ^ (jrow & 7))) << 4);
                uint32_t b0, b1, b2, b3, c0, c1, c2, c3;
                LDMATRIX_X4_T(b0, b1, b2, b3, sV + voff);
                LDMATRIX_X4_T(c0, c1, c2, c3, sV + 4096 + voff);
#pragma unroll
                for (int mi = 0; mi < 2; mi++) {
                    MMA_BF16(acc[mi][2 * nfp],     ah[mi][0], ah[mi][1], ah[mi][2], ah[mi][3], b0, b1);
                    MMA_BF16(acc[mi][2 * nfp + 1], ah[mi][0], ah[mi][1], ah[mi][2], ah[mi][3], b2, b3);
                    MMA_BF16(acc[mi][2 * nfp],     al[mi][0], al[mi][1], al[mi][2], al[mi][3], b0, b1);
                    MMA_BF16(acc[mi][2 * nfp + 1], al[mi][0], al[mi][1], al[mi][2], al[mi][3], b2, b3);
                    MMA_BF16(acc[mi][2 * nfp],     ah[mi][0], ah[mi][1], ah[mi][2], ah[mi][3], c0, c1);
                    MMA_BF16(acc[mi][2 * nfp + 1], ah[mi][0], ah[mi][1], ah[mi][2], ah[mi][3], c2, c3);
                }
            }
        }
        __syncthreads();
        if (c + 2 < NC) load_chunk(c + 2, c & 1);
    }

    // write O (cols [512,1024))
    const int qrow = lane >> 2, qcol2 = (lane & 3) * 2;
#pragma unroll
    for (int nf = 0; nf < 8; nf++) {
        const int c = 512 + H * 64 + nf * 8 + qcol2;
#pragma unroll
        for (int mi = 0; mi < 2; mi++) {
            const int i = i0w + mi * 16 + qrow;
            const size_t t0 = (size_t)(r * 256 + i) * OLD + c;
            const size_t t1 = (size_t)(r * 256 + i + 8) * OLD + c;
            split2_store(g_Ohi + t0, g_Olo + t0, acc[mi][nf][0], acc[mi][nf][1]);
            split2_store(g_Ohi + t1, g_Olo + t1, acc[mi][nf][2], acc[mi][nf][3]);
        }
    }
}

// ---------------------------------------------------------------------------
extern "C" void kernel_launch(void* const* d_in, const int* in_sizes, int n_in,
                              void* d_out, int out_size)
{
    const float* x      = (const float*)d_in[0];
    const float* wq_w   = (const float*)d_in[1];
    const float* wkv_w  = (const float*)d_in[2];
    const float* wout_w = (const float*)d_in[3];
    const float* wout_b = (const float*)d_in[4];
    const float* hq_w   = (const float*)d_in[5];
    const float* hkv_w  = (const float*)d_in[6];
    const float* hout_w = (const float*)d_in[7];
    const float* hout_b = (const float*)d_in[8];
    float* out = (float*)d_out;

    __nv_bfloat16 *xh, *xl, *Bph, *Bpl, *Ph, *Pl, *Ohi, *Olo, *Boh, *Bol;
    cudaGetSymbolAddress((void**)&xh, g_xh);
    cudaGetSymbolAddress((void**)&xl, g_xl);
    cudaGetSymbolAddress((void**)&Bph, g_Bph);
    cudaGetSymbolAddress((void**)&Bpl, g_Bpl);
    cudaGetSymbolAddress((void**)&Ph, g_Ph);
    cudaGetSymbolAddress((void**)&Pl, g_Pl);
    cudaGetSymbolAddress((void**)&Ohi, g_Ohi);
    cudaGetSymbolAddress((void**)&Olo, g_Olo);
    cudaGetSymbolAddress((void**)&Boh, g_Boh);
    cudaGetSymbolAddress((void**)&Bol, g_Bol);

    cudaFuncSetAttribute(gemm_mma, cudaFuncAttributeMaxDynamicSharedMemorySize, GEMM_SMEM);
    cudaFuncSetAttribute(attn_w_mma, cudaFuncAttributeMaxDynamicSharedMemorySize, ATTNW_SMEM);
    cudaFuncSetAttribute(dots_h_mma, cudaFuncAttributeMaxDynamicSharedMemorySize, DOTS_SMEM);
    cudaFuncSetAttribute(av_h_mma, cudaFuncAttributeMaxDynamicSharedMemorySize, AV_SMEM);

    // 1) splits + weight panels
    split_f32_kernel<<<4096, 256>>>(x, xh, xl, (size_t)NTOK * DIMD);
    build_Bp_kernel<<<3072, 256>>>(wq_w, wkv_w, hq_w, hkv_w);
    build_Bo_kernel<<<1024, 256>>>(wout_w, hout_w);

    // 2) projections -> P (bf16 hi/lo)
    gemm_mma<<<dim3(24, 256), 256, GEMM_SMEM>>>(xh, xl, DIMD, Bph, Bpl, DIMD,
                                                nullptr, Ph, Pl, PLD, DIMD,
                                                nullptr, nullptr);

    // 3) column attention (w branch) -> O cols [0,512)
    attn_w_mma<<<dim3(256, 8), 256, ATTNW_SMEM>>>();

    // 4) tied row attention (h branch) -> O cols [512,1024)
    dots_h_mma<<<dim3(4, 8, 4), 256, DOTS_SMEM>>>();
    softmax_h_kernel<<<2048, 256>>>();
    av_h_mma<<<dim3(128, 8), 256, AV_SMEM>>>();

    // 5) out = O @ [wout;hout] + biases
    gemm_mma<<<dim3(2, 256), 256, GEMM_SMEM>>>(Ohi, Olo, OLD, Boh, Bol, 1024,
                                               out, nullptr, nullptr, DIMD, 1024,
                                               wout_b, hout_b);
}

// round 5
// speedup vs baseline: 2.0490x; 1.0831x over previous
#include <cuda_runtime.h>
#include <cuda_bf16.h>
#include <cstdint>

#define NTOK  32768
#define DIMD  256
#define HEADS 8
#define MSAH  128
#define MSAW  256
#define PLD   3072   // P cols: [wq(512) | wk@512 | wv@1024 | hq@1536 | hk@2048 | hv@2560]
#define OLD   1024   // O cols: [Ow(512) | Oh(512)]
#define TSC   0.011048543456039806f  // 64^-0.5 * 128^-0.5

// ---------------------------------------------------------------------------
// Scratch
// ---------------------------------------------------------------------------
__device__ __nv_bfloat16 g_Ph[(size_t)NTOK * PLD];    // projections hi (201MB)
__device__ __nv_bfloat16 g_Pl[(size_t)NTOK * PLD];    // projections lo
__device__ float g_Shp[4 * HEADS * 256 * 256];        // tied-attn logit partials (8MB)
__device__ __nv_bfloat16 g_Shh[HEADS * 256 * 256];    // tied-attn probs hi/lo
__device__ __nv_bfloat16 g_Shl[HEADS * 256 * 256];
__device__ __nv_bfloat16 g_xh[(size_t)NTOK * DIMD];
__device__ __nv_bfloat16 g_xl[(size_t)NTOK * DIMD];
__device__ __nv_bfloat16 g_Bph[3072 * 256];
__device__ __nv_bfloat16 g_Bpl[3072 * 256];
__device__ __nv_bfloat16 g_Ohi[(size_t)NTOK * OLD];
__device__ __nv_bfloat16 g_Olo[(size_t)NTOK * OLD];
__device__ __nv_bfloat16 g_Boh[256 * 1024];
__device__ __nv_bfloat16 g_Bol[256 * 1024];

// ---------------------------------------------------------------------------
// PTX helpers (compute_103-safe)
// ---------------------------------------------------------------------------
__device__ __forceinline__ uint32_t smem_to_u32(const void* p) {
    uint32_t a;
    asm("{ .reg .u64 t; cvta.to.shared.u64 t, %1; cvt.u32.u64 %0, t; }" : "=r"(a) : "l"(p));
    return a;
}
#define CP_ASYNC16(dst, src) \
    asm volatile("cp.async.cg.shared.global [%0], [%1], 16;" :: "r"(dst), "l"(src) : "memory")
#define CP_COMMIT() asm volatile("cp.async.commit_group;" ::: "memory")
#define CP_WAIT0()  asm volatile("cp.async.wait_group 0;" ::: "memory")
#define CP_WAIT1()  asm volatile("cp.async.wait_group 1;" ::: "memory")

#define LDMATRIX_X4(d0, d1, d2, d3, addr) \
    asm volatile("ldmatrix.sync.aligned.m8n8.x4.shared.b16 {%0,%1,%2,%3}, [%4];" \
        : "=r"(d0), "=r"(d1), "=r"(d2), "=r"(d3) : "r"(addr))
#define LDMATRIX_X4_T(d0, d1, d2, d3, addr) \
    asm volatile("ldmatrix.sync.aligned.m8n8.x4.trans.shared.b16 {%0,%1,%2,%3}, [%4];" \
        : "=r"(d0), "=r"(d1), "=r"(d2), "=r"(d3) : "r"(addr))

#define MMA_BF16(c, a0, a1, a2, a3, b0, b1) \
    asm volatile("mma.sync.aligned.m16n8k16.row.col.f32.bf16.bf16.f32 " \
        "{%0,%1,%2,%3}, {%4,%5,%6,%7}, {%8,%9}, {%0,%1,%2,%3};" \
        : "+f"((c)[0]), "+f"((c)[1]), "+f"((c)[2]), "+f"((c)[3]) \
        : "r"(a0), "r"(a1), "r"(a2), "r"(a3), "r"(b0), "r"(b1))

__device__ __forceinline__ uint32_t pack_bf16x2(float lo, float hi) {
    __nv_bfloat162 t = __floats2bfloat162_rn(lo, hi);
    return *reinterpret_cast<uint32_t*>(&t);
}
__device__ __forceinline__ void split2_store(__nv_bfloat16* hi, __nv_bfloat16* lo,
                                             float a, float b) {
    __nv_bfloat16 ha = __float2bfloat16(a), hb = __float2bfloat16(b);
    __nv_bfloat162 h; h.x = ha; h.y = hb;
    *reinterpret_cast<__nv_bfloat162*>(hi) = h;
    __nv_bfloat162 l;
    l.x = __float2bfloat16(a - __bfloat162float(ha));
    l.y = __float2bfloat16(b - __bfloat162float(hb));
    *reinterpret_cast<__nv_bfloat162*>(lo) = l;
}

// ---------------------------------------------------------------------------
// Shared 128x128 tile compute: one 32-k chunk (granules 0-3 hi, 4-7 lo).
// Warp grid 4(m) x 2(n); warp tile 32x64; 3 MMA combos per fragment pair.
// ---------------------------------------------------------------------------
__device__ __forceinline__ void compute_chunk128(uint32_t sAst, uint32_t sBst,
                                                 int lane, int wm, int wn,
                                                 float acc[2][8][4])
{
#pragma unroll
    for (int kb = 0; kb < 2; kb++) {
        const int lg = kb * 2 + (lane >> 4);
        uint32_t ah[2][4], al[2][4];
#pragma unroll
        for (int mi = 0; mi < 2; mi++) {
            const int row = wm * 32 + mi * 16 + (lane & 15);
            LDMATRIX_X4(ah[mi][0], ah[mi][1], ah[mi][2], ah[mi][3],
                        sAst + row * 128 + (((lg) ^ (row & 7)) << 4));
            LDMATRIX_X4(al[mi][0], al[mi][1], al[mi][2], al[mi][3],
                        sAst + row * 128 + (((lg + 4) ^ (row & 7)) << 4));
        }
#pragma unroll
        for (int nf = 0; nf < 4; nf++) {
            const int row = wn * 64 + nf * 16 + (lane & 15);
            uint32_t b0, b1, b2, b3, c0, c1, c2, c3;
            LDMATRIX_X4(b0, b1, b2, b3, sBst + row * 128 + (((lg) ^ (row & 7)) << 4));
            LDMATRIX_X4(c0, c1, c2, c3, sBst + row * 128 + (((lg + 4) ^ (row & 7)) << 4));
#pragma unroll
            for (int mi = 0; mi < 2; mi++) {
                MMA_BF16(acc[mi][2 * nf],     ah[mi][0], ah[mi][1], ah[mi][2], ah[mi][3], b0, b2);
                MMA_BF16(acc[mi][2 * nf + 1], ah[mi][0], ah[mi][1], ah[mi][2], ah[mi][3], b1, b3);
                MMA_BF16(acc[mi][2 * nf],     al[mi][0], al[mi][1], al[mi][2], al[mi][3], b0, b2);
                MMA_BF16(acc[mi][2 * nf + 1], al[mi][0], al[mi][1], al[mi][2], al[mi][3], b1, b3);
                MMA_BF16(acc[mi][2 * nf],     ah[mi][0], ah[mi][1], ah[mi][2], ah[mi][3], c0, c2);
                MMA_BF16(acc[mi][2 * nf + 1], ah[mi][0], ah[mi][1], ah[mi][2], ah[mi][3], c1, c3);
            }
        }
    }
}

// ---------------------------------------------------------------------------
// Fused hi/lo split-bf16 GEMM. 2 CTAs/SM (reg cap 128) for latency hiding.
// ---------------------------------------------------------------------------
#define GEMM_SMEM (3 * 32768)   // 96 KB (3 stages x (A 16KB + B 16KB))

__global__ __launch_bounds__(256, 2)
void gemm_mma(const __nv_bfloat16* __restrict__ Ah, const __nv_bfloat16* __restrict__ Al, int lda,
              const __nv_bfloat16* __restrict__ Bh, const __nv_bfloat16* __restrict__ Bl, int ldb,
              float* __restrict__ C,
              __nv_bfloat16* __restrict__ Chi, __nv_bfloat16* __restrict__ Clo,
              int ldc, int K,
              const float* __restrict__ bias1, const float* __restrict__ bias2)
{
    extern __shared__ char smem[];
    const uint32_t sb = smem_to_u32(smem);
    const int tid = threadIdx.x, lane = tid & 31, wid = tid >> 5;
    const int wm = wid & 3, wn = wid >> 2;
    const int m0 = blockIdx.y * 128, j0 = blockIdx.x * 128;
    const int NC = K >> 5;

    float acc[2][8][4];
#pragma unroll
    for (int i = 0; i < 2; i++)
#pragma unroll
        for (int j = 0; j < 8; j++)
#pragma unroll
            for (int u = 0; u < 4; u++) acc[i][j][u] = 0.f;

    auto load_chunk = [&](int c, int s) {
        const int kc = c << 5;
        const uint32_t sA = sb + s * 32768, sB = sA + 16384;
#pragma unroll
        for (int i = 0; i < 4; i++) {
            const int id = tid + i * 256;
            const int row = id & 127, g = id >> 7;
            const uint32_t off = row * 128 + ((g ^ (row & 7)) << 4);
            const __nv_bfloat16* Asrc = (g < 4) ? Ah : Al;
            const __nv_bfloat16* Bsrc = (g < 4) ? Bh : Bl;
            CP_ASYNC16(sA + off, Asrc + (size_t)(m0 + row) * lda + kc + (g & 3) * 8);
            CP_ASYNC16(sB + off, Bsrc + (size_t)(j0 + row) * ldb + kc + (g & 3) * 8);
        }
        CP_COMMIT();
    };

    load_chunk(0, 0);
    load_chunk(1, 1);
    for (int c = 0; c < NC; c++) {
        if (c < NC - 1) { CP_WAIT1(); } else { CP_WAIT0(); }
        __syncthreads();
        if (c + 2 < NC) load_chunk(c + 2, (c + 2) % 3);
        const uint32_t sA = sb + (c % 3) * 32768;
        compute_chunk128(sA, sA + 16384, lane, wm, wn, acc);
    }

    const int qrow = lane >> 2, qcol2 = (lane & 3) * 2;
    if (C) {
#pragma unroll
        for (int nj = 0; nj < 8; nj++) {
            const int n = j0 + wn * 64 + nj * 8 + qcol2;
            float b0 = 0.f, b1 = 0.f;
            if (bias1) { b0 = bias1[n] + bias2[n]; b1 = bias1[n + 1] + bias2[n + 1]; }
#pragma unroll
            for (int mi = 0; mi < 2; mi++) {
                const int m = m0 + wm * 32 + mi * 16 + qrow;
                float2 v0, v1;
                v0.x = acc[mi][nj][0] + b0; v0.y = acc[mi][nj][1] + b1;
                v1.x = acc[mi][nj][2] + b0; v1.y = acc[mi][nj][3] + b1;
                *(float2*)(C + (size_t)m * ldc + n) = v0;
                *(float2*)(C + (size_t)(m + 8) * ldc + n) = v1;
            }
        }
    } else {
#pragma unroll
        for (int nj = 0; nj < 8; nj++) {
            const int n = j0 + wn * 64 + nj * 8 + qcol2;
#pragma unroll
            for (int mi = 0; mi < 2; mi++) {
                const int m = m0 + wm * 32 + mi * 16 + qrow;
                split2_store(Chi + (size_t)m * ldc + n, Clo + (size_t)m * ldc + n,
                             acc[mi][nj][0], acc[mi][nj][1]);
                split2_store(Chi + (size_t)(m + 8) * ldc + n, Clo + (size_t)(m + 8) * ldc + n,
                             acc[mi][nj][2], acc[mi][nj][3]);
            }
        }
    }
}

// ---------------------------------------------------------------------------
// splitters / weight-panel builders
// ---------------------------------------------------------------------------
__global__ void split_f32_kernel(const float* __restrict__ in,
                                 __nv_bfloat16* __restrict__ hi,
                                 __nv_bfloat16* __restrict__ lo, size_t n)
{
    size_t i = (size_t)blockIdx.x * blockDim.x + threadIdx.x;
    const size_t stride = (size_t)gridDim.x * blockDim.x;
    for (; i < n; i += stride) {
        float v = in[i];
        __nv_bfloat16 h = __float2bfloat16(v);
        hi[i] = h;
        lo[i] = __float2bfloat16(v - __bfloat162float(h));
    }
}
__global__ void build_Bp_kernel(const float* __restrict__ wq, const float* __restrict__ wkv,
                                const float* __restrict__ hq, const float* __restrict__ hkv)
{
    const int idx = blockIdx.x * 256 + threadIdx.x;   // k*3072 + n
    const int k = idx / 3072, n = idx - k * 3072;
    float v;
    if (n < 512)       v = wq[k * 512 + n];
    else if (n < 1536) v = wkv[k * 1024 + (n - 512)];
    else if (n < 2048) v = hq[k * 512 + (n - 1536)];
    else               v = hkv[k * 1024 + (n - 2048)];
    __nv_bfloat16 h = __float2bfloat16(v);
    g_Bph[(size_t)n * 256 + k] = h;
    g_Bpl[(size_t)n * 256 + k] = __float2bfloat16(v - __bfloat162float(h));
}
__global__ void build_Bo_kernel(const float* __restrict__ wo, const float* __restrict__ ho)
{
    const int idx = blockIdx.x * 256 + threadIdx.x;   // k*256 + n
    const int k = idx >> 8, n = idx & 255;
    float v = (k < 512) ? wo[k * 256 + n] : ho[(k - 512) * 256 + n];
    __nv_bfloat16 h = __float2bfloat16(v);
    g_Boh[(size_t)n * 1024 + k] = h;
    g_Bol[(size_t)n * 1024 + k] = __float2bfloat16(v - __bfloat162float(h));
}

// ---------------------------------------------------------------------------
// Column attention (w branch). One block per (cw, H). 1 CTA/SM (reg-heavy).
// ---------------------------------------------------------------------------
#define ATTNW_SMEM (6 * 16384)   // 96 KB

__global__ __launch_bounds__(256) void attn_w_mma()
{
    extern __shared__ char smem[];
    const uint32_t sb = smem_to_u32(smem);
    const int cw = blockIdx.x, H = blockIdx.y;
    const int tid = threadIdx.x, lane = tid & 31, wid = tid >> 5;

#pragma unroll
    for (int t = 0; t < 6; t++) {
        const __nv_bfloat16* src = (t & 1) ? g_Pl : g_Ph;
        const int coff = (t >> 1) * 512 + H * 64;
#pragma unroll
        for (int i = 0; i < 4; i++) {
            const int id = tid + i * 256;
            const int row = id & 127, g = id >> 7;
            CP_ASYNC16(sb + t * 16384 + row * 128 + ((g ^ (row & 7)) << 4),
                       src + (size_t)(row * 256 + cw) * PLD + coff + g * 8);
        }
    }
    CP_COMMIT(); CP_WAIT0();
    __syncthreads();

    const uint32_t sQh = sb, sQl = sb + 16384, sKh = sb + 32768,
                   sKl = sb + 49152, sVh = sb + 65536, sVl = sb + 81920;
    const int i0w = wid * 16;

    float acc[16][4];
#pragma unroll
    for (int i = 0; i < 16; i++)
#pragma unroll
        for (int u = 0; u < 4; u++) acc[i][u] = 0.f;

#pragma unroll
    for (int kb = 0; kb < 4; kb++) {
        const int lg = kb * 2 + (lane >> 4);
        const int ar = i0w + (lane & 15);
        const uint32_t aoff = ar * 128 + ((lg ^ (ar & 7)) << 4);
        uint32_t ah[4], al[4];
        LDMATRIX_X4(ah[0], ah[1], ah[2], ah[3], sQh + aoff);
        LDMATRIX_X4(al[0], al[1], al[2], al[3], sQl + aoff);
#pragma unroll
        for (int nf = 0; nf < 8; nf++) {
            const int br = nf * 16 + (lane & 15);
            const uint32_t boff = br * 128 + ((lg ^ (br & 7)) << 4);
            uint32_t b0, b1, b2, b3, c0, c1, c2, c3;
            LDMATRIX_X4(b0, b1, b2, b3, sKh + boff);
            LDMATRIX_X4(c0, c1, c2, c3, sKl + boff);
            MMA_BF16(acc[2 * nf],     ah[0], ah[1], ah[2], ah[3], b0, b2);
            MMA_BF16(acc[2 * nf + 1], ah[0], ah[1], ah[2], ah[3], b1, b3);
            MMA_BF16(acc[2 * nf],     al[0], al[1], al[2], al[3], b0, b2);
            MMA_BF16(acc[2 * nf + 1], al[0], al[1], al[2], al[3], b1, b3);
            MMA_BF16(acc[2 * nf],     ah[0], ah[1], ah[2], ah[3], c0, c2);
            MMA_BF16(acc[2 * nf + 1], ah[0], ah[1], ah[2], ah[3], c1, c3);
        }
    }

    float mx0 = -1e30f, mx1 = -1e30f;
#pragma unroll
    for (int ni = 0; ni < 16; ni++) {
        acc[ni][0] *= 0.125f; acc[ni][1] *= 0.125f;
        acc[ni][2] *= 0.125f; acc[ni][3] *= 0.125f;
        mx0 = fmaxf(mx0, fmaxf(acc[ni][0], acc[ni][1]));
        mx1 = fmaxf(mx1, fmaxf(acc[ni][2], acc[ni][3]));
    }
    mx0 = fmaxf(mx0, __shfl_xor_sync(0xffffffffu, mx0, 1));
    mx0 = fmaxf(mx0, __shfl_xor_sync(0xffffffffu, mx0, 2));
    mx1 = fmaxf(mx1, __shfl_xor_sync(0xffffffffu, mx1, 1));
    mx1 = fmaxf(mx1, __shfl_xor_sync(0xffffffffu, mx1, 2));
    float s0 = 0.f, s1 = 0.f;
#pragma unroll
    for (int ni = 0; ni < 16; ni++) {
        float e;
        e = __expf(acc[ni][0] - mx0); acc[ni][0] = e; s0 += e;
        e = __expf(acc[ni][1] - mx0); acc[ni][1] = e; s0 += e;
        e = __expf(acc[ni][2] - mx1); acc[ni][2] = e; s1 += e;
        e = __expf(acc[ni][3] - mx1); acc[ni][3] = e; s1 += e;
    }
    s0 += __shfl_xor_sync(0xffffffffu, s0, 1);
    s0 += __shfl_xor_sync(0xffffffffu, s0, 2);
    s1 += __shfl_xor_sync(0xffffffffu, s1, 1);
    s1 += __shfl_xor_sync(0xffffffffu, s1, 2);
    const float inv0 = 1.f / s0, inv1 = 1.f / s1;

    uint32_t aph[8][4], apl[8][4];
#pragma unroll
    for (int kb = 0; kb < 8; kb++) {
        const int n0 = 2 * kb, n1 = n0 + 1;
        float p[8];
        p[0] = acc[n0][0] * inv0; p[1] = acc[n0][1] * inv0;
        p[2] = acc[n0][2] * inv1; p[3] = acc[n0][3] * inv1;
        p[4] = acc[n1][0] * inv0; p[5] = acc[n1][1] * inv0;
        p[6] = acc[n1][2] * inv1; p[7] = acc[n1][3] * inv1;
#pragma unroll
        for (int u = 0; u < 4; u++) {
            float a = p[2 * u], b = p[2 * u + 1];
            __nv_bfloat16 ha = __float2bfloat16(a), hb = __float2bfloat16(b);
            __nv_bfloat162 hh; hh.x = ha; hh.y = hb;
            aph[kb][u] = *reinterpret_cast<uint32_t*>(&hh);
            apl[kb][u] = pack_bf16x2(a - __bfloat162float(ha), b - __bfloat162float(hb));
        }
    }

    float acco[8][4];
#pragma unroll
    for (int i = 0; i < 8; i++)
#pragma unroll
        for (int u = 0; u < 4; u++) acco[i][u] = 0.f;

#pragma unroll
    for (int kb = 0; kb < 8; kb++) {
        const int jrow = kb * 16 + ((lane >> 3) & 1) * 8 + (lane & 7);
#pragma unroll
        for (int nfp = 0; nfp < 4; nfp++) {
            const int ncol = nfp * 16 + (lane >> 4) * 8;
            const uint32_t voff = jrow * 128 + ((((ncol >> 3) ^ (jrow & 7))) << 4);
            uint32_t b0, b1, b2, b3, c0, c1, c2, c3;
            LDMATRIX_X4_T(b0, b1, b2, b3, sVh + voff);
            LDMATRIX_X4_T(c0, c1, c2, c3, sVl + voff);
            MMA_BF16(acco[2 * nfp],     aph[kb][0], aph[kb][1], aph[kb][2], aph[kb][3], b0, b1);
            MMA_BF16(acco[2 * nfp + 1], aph[kb][0], aph[kb][1], aph[kb][2], aph[kb][3], b2, b3);
            MMA_BF16(acco[2 * nfp],     apl[kb][0], apl[kb][1], apl[kb][2], apl[kb][3], b0, b1);
            MMA_BF16(acco[2 * nfp + 1], apl[kb][0], apl[kb][1], apl[kb][2], apl[kb][3], b2, b3);
            MMA_BF16(acco[2 * nfp],     aph[kb][0], aph[kb][1], aph[kb][2], aph[kb][3], c0, c1);
            MMA_BF16(acco[2 * nfp + 1], aph[kb][0], aph[kb][1], aph[kb][2], aph[kb][3], c2, c3);
        }
    }

    const int r0 = i0w + (lane >> 2), r1 = r0 + 8;
#pragma unroll
    for (int nf = 0; nf < 8; nf++) {
        const int c = H * 64 + nf * 8 + (lane & 3) * 2;
        const size_t t0 = (size_t)(r0 * 256 + cw) * OLD + c;
        const size_t t1 = (size_t)(r1 * 256 + cw) * OLD + c;
        split2_store(g_Ohi + t0, g_Olo + t0, acco[nf][0], acco[nf][1]);
        split2_store(g_Ohi + t1, g_Olo + t1, acco[nf][2], acco[nf][3]);
    }
}

// ---------------------------------------------------------------------------
// Tied row attention dots: split-K over r. 2 CTAs/SM.
// ---------------------------------------------------------------------------
#define DOTS_SMEM (3 * 32768)

__global__ __launch_bounds__(256, 2) void dots_h_mma()
{
    extern __shared__ char smem[];
    const uint32_t sb = smem_to_u32(smem);
    const int tid = threadIdx.x, lane = tid & 31, wid = tid >> 5;
    const int wm = wid & 3, wn = wid >> 2;
    const int i0 = (blockIdx.x & 1) * 128, j0 = (blockIdx.x >> 1) * 128;
    const int H = blockIdx.y, sp = blockIdx.z;
    const int rbase = sp * 32;
    const int NC = 64;

    float acc[2][8][4];
#pragma unroll
    for (int i = 0; i < 2; i++)
#pragma unroll
        for (int j = 0; j < 8; j++)
#pragma unroll
            for (int u = 0; u < 4; u++) acc[i][j][u] = 0.f;

    auto load_chunk = [&](int c, int s) {
        const int r = rbase + (c >> 1), dhc = (c & 1) * 32;
        const size_t abase = ((size_t)(r * 256 + i0)) * PLD + 1536 + H * 64 + dhc;
        const size_t bbase = ((size_t)(r * 256 + j0)) * PLD + 2048 + H * 64 + dhc;
        const uint32_t sA = sb + s * 32768, sB = sA + 16384;
#pragma unroll
        for (int i = 0; i < 4; i++) {
            const int id = tid + i * 256;
            const int row = id & 127, g = id >> 7;
            const uint32_t off = row * 128 + ((g ^ (row & 7)) << 4);
            const __nv_bfloat16* src = (g < 4) ? g_Ph : g_Pl;
            CP_ASYNC16(sA + off, src + abase + (size_t)row * PLD + (g & 3) * 8);
            CP_ASYNC16(sB + off, src + bbase + (size_t)row * PLD + (g & 3) * 8);
        }
        CP_COMMIT();
    };

    load_chunk(0, 0);
    load_chunk(1, 1);
    for (int c = 0; c < NC; c++) {
        if (c < NC - 1) { CP_WAIT1(); } else { CP_WAIT0(); }
        __syncthreads();
        if (c + 2 < NC) load_chunk(c + 2, (c + 2) % 3);
        const uint32_t sA = sb + (c % 3) * 32768;
        compute_chunk128(sA, sA + 16384, lane, wm, wn, acc);
    }

    float* Cp = g_Shp + (size_t)sp * 524288 + (size_t)H * 65536;
    const int qrow = lane >> 2, qcol2 = (lane & 3) * 2;
#pragma unroll
    for (int nj = 0; nj < 8; nj++) {
        const int n = j0 + wn * 64 + nj * 8 + qcol2;
#pragma unroll
        for (int mi = 0; mi < 2; mi++) {
            const int m = i0 + wm * 32 + mi * 16 + qrow;
            float2 v0, v1;
            v0.x = acc[mi][nj][0]; v0.y = acc[mi][nj][1];
            v1.x = acc[mi][nj][2]; v1.y = acc[mi][nj][3];
            *(float2*)(Cp + m * 256 + n) = v0;
            *(float2*)(Cp + (m + 8) * 256 + n) = v1;
        }
    }
}

// Sum 4 partials, scale, softmax over 256, emit bf16 hi/lo probs.
__global__ __launch_bounds__(256) void softmax_h_kernel()
{
    const size_t base = (size_t)blockIdx.x * 256;
    const int t = threadIdx.x;
    __shared__ float red[256];
    float v = (g_Shp[base + t] + g_Shp[524288 + base + t] +
               g_Shp[2 * 524288 + base + t] + g_Shp[3 * 524288 + base + t]) * TSC;
    red[t] = v;
    __syncthreads();
#pragma unroll
    for (int s = 128; s > 0; s >>= 1) {
        if (t < s) red[t] = fmaxf(red[t], red[t + s]);
        __syncthreads();
    }
    const float m = red[0];
    __syncthreads();
    const float e = __expf(v - m);
    red[t] = e;
    __syncthreads();
#pragma unroll
    for (int s = 128; s > 0; s >>= 1) {
        if (t < s) red[t] += red[t + s];
        __syncthreads();
    }
    const float p = e / red[0];
    const __nv_bfloat16 h = __float2bfloat16(p);
    g_Shh[base + t] = h;
    g_Shl[base + t] = __float2bfloat16(p - __bfloat162float(h));
}

// ---------------------------------------------------------------------------
// Tied row attention AV. 2 CTAs/SM.
// ---------------------------------------------------------------------------
#define AV_SMEM (2 * 40960)   // 80 KB

__global__ __launch_bounds__(256, 2) void av_h_mma()
{
    extern __shared__ char smem[];
    const uint32_t sb = smem_to_u32(smem);
    const int r = blockIdx.x, H = blockIdx.y;
    const int tid = threadIdx.x, lane = tid & 31, wid = tid >> 5;
    const int i0w = wid * 32;
    const int NC = 8;

    float acc[2][8][4];
#pragma unroll
    for (int i = 0; i < 2; i++)
#pragma unroll
        for (int j = 0; j < 8; j++)
#pragma unroll
            for (int u = 0; u < 4; u++) acc[i][j][u] = 0.f;

    auto load_chunk = [&](int c, int s) {
        const int jc = c << 5;
        const uint32_t sA = sb + s * 40960, sV = sA + 32768;
#pragma unroll
        for (int i = 0; i < 8; i++) {
            const int id = tid + i * 256;
            const int row = id & 255, g = id >> 8;
            const __nv_bfloat16* src = (g < 4) ? g_Shh : g_Shl;
            CP_ASYNC16(sA + row * 128 + ((g ^ (row & 7)) << 4),
                       src + (size_t)H * 65536 + row * 256 + jc + (g & 3) * 8);
        }
#pragma unroll
        for (int i = 0; i < 2; i++) {
            const int id = tid + i * 256;
            const int jrow = id & 31, g = (id >> 5) & 7, half = id >> 8;
            const __nv_bfloat16* src = half ? g_Pl : g_Ph;
            CP_ASYNC16(sV + half * 4096 + jrow * 128 + ((g ^ (jrow & 7)) << 4),
                       src + (size_t)(r * 256 + jc + jrow) * PLD + 2560 + H * 64 + g * 8);
        }
        CP_COMMIT();
    };

    load_chunk(0, 0);
    load_chunk(1, 1);
    for (int c = 0; c < NC; c++) {
        if (c + 1 < NC) { CP_WAIT1(); } else { CP_WAIT0(); }
        __syncthreads();
        const uint32_t sA = sb + (c & 1) * 40960, sV = sA + 32768;
#pragma unroll
        for (int kb = 0; kb < 2; kb++) {
            const int lg = kb * 2 + (lane >> 4);
            uint32_t ah[2][4], al[2][4];
#pragma unroll
            for (int mi = 0; mi < 2; mi++) {
                const int row = i0w + mi * 16 + (lane & 15);
                LDMATRIX_X4(ah[mi][0], ah[mi][1], ah[mi][2], ah[mi][3],
                            sA + row * 128 + ((lg ^ (row & 7)) << 4));
                LDMATRIX_X4(al[mi][0], al[mi][1], al[mi][2], al[mi][3],
                            sA + row * 128 + (((lg + 4) ^ (row & 7)) << 4));
            }
            const int jrow = kb * 16 + ((lane >> 3) & 1) * 8 + (lane & 7);
#pragma unroll
            for (int nfp = 0; nfp < 4; nfp++) {
                const int ncol = nfp * 16 + (lane >> 4) * 8;
                const uint32_t voff = jrow * 128 + ((((ncol >> 3) ^ (jrow & 7))) << 4);
                uint32_t b0, b1, b2, b3, c0, c1, c2, c3;
                LDMATRIX_X4_T(b0, b1, b2, b3, sV + voff);
                LDMATRIX_X4_T(c0, c1, c2, c3, sV + 4096 + voff);
#pragma unroll
                for (int mi = 0; mi < 2; mi++) {
                    MMA_BF16(acc[mi][2 * nfp],     ah[mi][0], ah[mi][1], ah[mi][2], ah[mi][3], b0, b1);
                    MMA_BF16(acc[mi][2 * nfp + 1], ah[mi][0], ah[mi][1], ah[mi][2], ah[mi][3], b2, b3);
                    MMA_BF16(acc[mi][2 * nfp],     al[mi][0], al[mi][1], al[mi][2], al[mi][3], b0, b1);
                    MMA_BF16(acc[mi][2 * nfp + 1], al[mi][0], al[mi][1], al[mi][2], al[mi][3], b2, b3);
                    MMA_BF16(acc[mi][2 * nfp],     ah[mi][0], ah[mi][1], ah[mi][2], ah[mi][3], c0, c1);
                    MMA_BF16(acc[mi][2 * nfp + 1], ah[mi][0], ah[mi][1], ah[mi][2], ah[mi][3], c2, c3);
                }
            }
        }
        __syncthreads();
        if (c + 2 < NC) load_chunk(c + 2, c & 1);
    }

    const int qrow = lane >> 2, qcol2 = (lane & 3) * 2;
#pragma unroll
    for (int nf = 0; nf < 8; nf++) {
        const int c = 512 + H * 64 + nf * 8 + qcol2;
#pragma unroll
        for (int mi = 0; mi < 2; mi++) {
            const int i = i0w + mi * 16 + qrow;
            const size_t t0 = (size_t)(r * 256 + i) * OLD + c;
            const size_t t1 = (size_t)(r * 256 + i + 8) * OLD + c;
            split2_store(g_Ohi + t0, g_Olo + t0, acc[mi][nf][0], acc[mi][nf][1]);
            split2_store(g_Ohi + t1, g_Olo + t1, acc[mi][nf][2], acc[mi][nf][3]);
        }
    }
}

// ---------------------------------------------------------------------------
extern "C" void kernel_launch(void* const* d_in, const int* in_sizes, int n_in,
                              void* d_out, int out_size)
{
    const float* x      = (const float*)d_in[0];
    const float* wq_w   = (const float*)d_in[1];
    const float* wkv_w  = (const float*)d_in[2];
    const float* wout_w = (const float*)d_in[3];
    const float* wout_b = (const float*)d_in[4];
    const float* hq_w   = (const float*)d_in[5];
    const float* hkv_w  = (const float*)d_in[6];
    const float* hout_w = (const float*)d_in[7];
    const float* hout_b = (const float*)d_in[8];
    float* out = (float*)d_out;

    __nv_bfloat16 *xh, *xl, *Bph, *Bpl, *Ph, *Pl, *Ohi, *Olo, *Boh, *Bol;
    cudaGetSymbolAddress((void**)&xh, g_xh);
    cudaGetSymbolAddress((void**)&xl, g_xl);
    cudaGetSymbolAddress((void**)&Bph, g_Bph);
    cudaGetSymbolAddress((void**)&Bpl, g_Bpl);
    cudaGetSymbolAddress((void**)&Ph, g_Ph);
    cudaGetSymbolAddress((void**)&Pl, g_Pl);
    cudaGetSymbolAddress((void**)&Ohi, g_Ohi);
    cudaGetSymbolAddress((void**)&Olo, g_Olo);
    cudaGetSymbolAddress((void**)&Boh, g_Boh);
    cudaGetSymbolAddress((void**)&Bol, g_Bol);

    cudaFuncSetAttribute(gemm_mma, cudaFuncAttributeMaxDynamicSharedMemorySize, GEMM_SMEM);
    cudaFuncSetAttribute(attn_w_mma, cudaFuncAttributeMaxDynamicSharedMemorySize, ATTNW_SMEM);
    cudaFuncSetAttribute(dots_h_mma, cudaFuncAttributeMaxDynamicSharedMemorySize, DOTS_SMEM);
    cudaFuncSetAttribute(av_h_mma, cudaFuncAttributeMaxDynamicSharedMemorySize, AV_SMEM);

    // 1) splits + weight panels
    split_f32_kernel<<<4096, 256>>>(x, xh, xl, (size_t)NTOK * DIMD);
    build_Bp_kernel<<<3072, 256>>>(wq_w, wkv_w, hq_w, hkv_w);
    build_Bo_kernel<<<1024, 256>>>(wout_w, hout_w);

    // 2) projections -> P (bf16 hi/lo)
    gemm_mma<<<dim3(24, 256), 256, GEMM_SMEM>>>(xh, xl, DIMD, Bph, Bpl, DIMD,
                                                nullptr, Ph, Pl, PLD, DIMD,
                                                nullptr, nullptr);

    // 3) column attention (w branch) -> O cols [0,512)
    attn_w_mma<<<dim3(256, 8), 256, ATTNW_SMEM>>>();

    // 4) tied row attention (h branch) -> O cols [512,1024)
    dots_h_mma<<<dim3(4, 8, 4), 256, DOTS_SMEM>>>();
    softmax_h_kernel<<<2048, 256>>>();
    av_h_mma<<<dim3(128, 8), 256, AV_SMEM>>>();

    // 5) out = O @ [wout;hout] + biases
    gemm_mma<<<dim3(2, 256), 256, GEMM_SMEM>>>(Ohi, Olo, OLD, Boh, Bol, 1024,
                                               out, nullptr, nullptr, DIMD, 1024,
                                               wout_b, hout_b);
}